// round 13
// baseline (speedup 1.0000x reference)
#include <cuda_runtime.h>
#include <cuda_fp16.h>
#include <math.h>
#include <stdint.h>

#define NN 50000
#define EE 800000
#define DH 256
#define NL 8
#define NTILES ((NN + 127) / 128)        // 391
#define NPAD (NTILES * 128)              // 50048
#define NT2 ((NN + 255) / 256)           // 196
#define NPAD2 (NT2 * 256)                // 50176

// ---------------- scratch ----------------
__device__ __align__(16) __half g_h16[(size_t)NN * DH];          // fp16 h_out (pre-norm)
__device__ __align__(16) __half g_hn[(size_t)NPAD2 * DH];        // fp16 relu(norm(h)) / x0
__device__ __align__(16) __half g_a[(size_t)NPAD * 512];         // fp16 A [node][k] k<256 agg, k>=256 x0
__device__ __align__(16) __half g_bh[(size_t)NL * 512 * 256];    // B' hi
__device__ __align__(16) __half g_bl[(size_t)NL * 512 * 256];    // B' lo
__device__ __align__(16) __half g_x16[(size_t)NPAD * 128];       // fp16 x
__device__ __align__(16) __half g_w1h[128 * 256], g_w1l[128 * 256];
__device__ __align__(16) __half g_w2h[256 * 128], g_w2l[256 * 128];
__device__ float g_dis[NN];
__device__ int   g_counts[NN];
__device__ int   g_cursor[NN];
__device__ int   g_rowptr[NN + 1];
__device__ int   g_csr[EE];
__device__ float g_part[NTILES + 8];
__device__ float g_part2[NTILES + 8];

// ---------------- helpers ----------------
__device__ __forceinline__ uint32_t s2u(const void* p) {
    uint32_t a;
    asm("{ .reg .u64 t; cvta.to.shared.u64 t, %1; cvt.u32.u64 %0, t; }" : "=r"(a) : "l"(p));
    return a;
}
__device__ __forceinline__ void cp16(uint32_t dst, const void* src) {
    asm volatile("cp.async.cg.shared.global [%0], [%1], 16;" :: "r"(dst), "l"(src) : "memory");
}
#define CP_COMMIT() asm volatile("cp.async.commit_group;" ::: "memory")
#define CP_WAIT(n)  asm volatile("cp.async.wait_group %0;" :: "n"(n) : "memory")

#define LDSM4(r0,r1,r2,r3,a) \
    asm volatile("ldmatrix.sync.aligned.m8n8.x4.shared.b16 {%0,%1,%2,%3}, [%4];" \
                 : "=r"(r0),"=r"(r1),"=r"(r2),"=r"(r3) : "r"(a))
#define LDSM4T(r0,r1,r2,r3,a) \
    asm volatile("ldmatrix.sync.aligned.m8n8.x4.trans.shared.b16 {%0,%1,%2,%3}, [%4];" \
                 : "=r"(r0),"=r"(r1),"=r"(r2),"=r"(r3) : "r"(a))
#define MMA_F16(c,a,b0,b1) \
    asm volatile("mma.sync.aligned.m16n8k16.row.col.f32.f16.f16.f32 " \
                 "{%0,%1,%2,%3}, {%4,%5,%6,%7}, {%8,%9}, {%0,%1,%2,%3};" \
                 : "+f"((c)[0]),"+f"((c)[1]),"+f"((c)[2]),"+f"((c)[3]) \
                 : "r"((a)[0]),"r"((a)[1]),"r"((a)[2]),"r"((a)[3]),"r"(b0),"r"(b1))

__device__ __forceinline__ void split_h(float v, __half& h, __half& l) {
    h = __float2half_rn(v);
    l = __float2half_rn(v - __half2float(h));
}

// ---------------- graph preprocessing ----------------
__global__ void k_init(int n) {
    int i = blockIdx.x * blockDim.x + threadIdx.x;
    if (i < n) { g_counts[i] = 0; g_cursor[i] = 0; }
}
__global__ void k_count(const int* __restrict__ col, int E) {
    int e = blockIdx.x * blockDim.x + threadIdx.x;
    if (e < E) atomicAdd(&g_counts[col[e]], 1);
}
__global__ void k_scan(int n, int E) {
    __shared__ int sh[1024];
    int tid = threadIdx.x;
    int C = (n + 1023) >> 10;
    int base = tid * C;
    int s = 0;
    for (int i = 0; i < C; i++) { int idx = base + i; if (idx < n) s += g_counts[idx]; }
    sh[tid] = s; __syncthreads();
    for (int off = 1; off < 1024; off <<= 1) {
        int v = (tid >= off) ? sh[tid - off] : 0;
        __syncthreads();
        sh[tid] += v;
        __syncthreads();
    }
    int run = (tid > 0) ? sh[tid - 1] : 0;
    for (int i = 0; i < C; i++) {
        int idx = base + i;
        if (idx < n) {
            g_rowptr[idx] = run;
            int c = g_counts[idx];
            run += c;
            g_dis[idx] = rsqrtf((float)(c + 1));
        }
    }
    if (tid == 0) g_rowptr[n] = E;
}
__global__ void k_scatter(const int* __restrict__ row, const int* __restrict__ col, int E) {
    int e = blockIdx.x * blockDim.x + threadIdx.x;
    if (e < E) {
        int c = col[e];
        int p = g_rowptr[c] + atomicAdd(&g_cursor[c], 1);
        g_csr[p] = row[e];
    }
}

// ---------------- weight / input prep ----------------
__global__ void k_prep_b(const float* __restrict__ w1, const float* __restrict__ w2) {
    int idx = blockIdx.x * blockDim.x + threadIdx.x;
    if (idx >= NL * 512 * 256) return;
    int n = idx & 255;
    int k = (idx >> 8) & 511;
    int l = idx >> 17;
    float beta = logf(1.0f / (float)(l + 1) + 1.0f);
    float v = (k < 256) ? w1[(l << 16) + (k << 8) + n]
                        : w2[(l << 16) + ((k - 256) << 8) + n];
    float val = 0.5f * beta * v;
    if (k == n || k == n + 256) val += 0.5f * (1.0f - beta);
    split_h(val, g_bh[idx], g_bl[idx]);
}
__global__ void k_prep_x(const float* __restrict__ x, int total) {
    int i = blockIdx.x * blockDim.x + threadIdx.x;
    if (i < total) g_x16[i] = __float2half_rn(x[i]);
}
__global__ void k_prep_w(const float* __restrict__ w1, const float* __restrict__ w2) {
    int i = blockIdx.x * blockDim.x + threadIdx.x;
    if (i < 128 * 256) {
        split_h(w1[i], g_w1h[i], g_w1l[i]);
    } else if (i < 128 * 256 + 256 * 128) {
        int j = i - 128 * 256;
        split_h(w2[j], g_w2h[j], g_w2l[j]);
    }
}

// ---------------- CSR gather (fp16 in) -> fp16 A rows (k 0..255) ----------------
__global__ __launch_bounds__(256) void k_gather(int n) {
    int w = (blockIdx.x * blockDim.x + threadIdx.x) >> 5;
    int lane = threadIdx.x & 31;
    if (w >= n) return;
    const uint4* __restrict__ hn = (const uint4*)g_hn;
    float dc = g_dis[w];
    float a[8];
    {
        uint4 v = hn[w * 32 + lane];
        const __half2* ph = (const __half2*)&v;
#pragma unroll
        for (int j = 0; j < 4; j++) {
            float2 f = __half22float2(ph[j]);
            a[2 * j] = dc * f.x; a[2 * j + 1] = dc * f.y;
        }
    }
    int beg = g_rowptr[w], end = g_rowptr[w + 1];
    int i = beg;
    for (; i + 3 < end; i += 4) {
        int s0 = g_csr[i], s1 = g_csr[i + 1], s2 = g_csr[i + 2], s3 = g_csr[i + 3];
        float w0 = g_dis[s0], w1 = g_dis[s1], w2 = g_dis[s2], w3 = g_dis[s3];
        uint4 p = hn[s0 * 32 + lane], q = hn[s1 * 32 + lane];
        uint4 r = hn[s2 * 32 + lane], t = hn[s3 * 32 + lane];
        const __half2* pp = (const __half2*)&p;
        const __half2* qq = (const __half2*)&q;
        const __half2* rr = (const __half2*)&r;
        const __half2* tt = (const __half2*)&t;
#pragma unroll
        for (int j = 0; j < 4; j++) {
            float2 fp = __half22float2(pp[j]);
            float2 fq = __half22float2(qq[j]);
            float2 fr = __half22float2(rr[j]);
            float2 ft = __half22float2(tt[j]);
            a[2 * j]     = fmaf(w0, fp.x, fmaf(w1, fq.x, fmaf(w2, fr.x, fmaf(w3, ft.x, a[2 * j]))));
            a[2 * j + 1] = fmaf(w0, fp.y, fmaf(w1, fq.y, fmaf(w2, fr.y, fmaf(w3, ft.y, a[2 * j + 1]))));
        }
    }
    for (; i < end; i++) {
        int s0 = g_csr[i];
        float w0 = g_dis[s0];
        uint4 p = hn[s0 * 32 + lane];
        const __half2* pp = (const __half2*)&p;
#pragma unroll
        for (int j = 0; j < 4; j++) {
            float2 fp = __half22float2(pp[j]);
            a[2 * j]     = fmaf(w0, fp.x, a[2 * j]);
            a[2 * j + 1] = fmaf(w0, fp.y, a[2 * j + 1]);
        }
    }
    size_t ro = (size_t)w * 512 + lane * 8;
    __half hh[8];
#pragma unroll
    for (int j = 0; j < 8; j++) hh[j] = __float2half_rn(a[j] * dc);
    *(uint4*)&g_a[ro] = *(uint4*)hh;
}

// ---------------- layer GEMM: fp16 2-pass, 128m x 256n, K=512 (8x64) ----------------
#define STAGE 81920u
#define SMTOT 163840
__global__ __launch_bounds__(256, 1) void k_mma(int layer, int nvalid) {
    extern __shared__ char smem[];
    uint32_t sb = s2u(smem);
    const int tid = threadIdx.x, lane = tid & 31, wid = tid >> 5;
    const int T = blockIdx.x;

    const __half* __restrict__ Ag = g_a + (size_t)T * 128 * 512;
    const __half* __restrict__ Bgh = g_bh + (size_t)layer * 512 * 256;
    const __half* __restrict__ Bgl = g_bl + (size_t)layer * 512 * 256;

    auto load_chunk = [&](int c, int st) {
        uint32_t s0 = sb + st * STAGE;
#pragma unroll
        for (int i = 0; i < 4; i++) {
            int e = tid + i * 256;
            int m = e >> 3, kc = e & 7;
            uint32_t da = (uint32_t)(m * 128 + ((kc ^ (m & 7)) << 4));
            cp16(s0 + da, Ag + (size_t)m * 512 + c * 64 + kc * 8);
        }
#pragma unroll
        for (int i = 0; i < 8; i++) {
            int e = tid + i * 256;
            int k = e >> 5, ncol = e & 31;
            int nhalf = ncol >> 4, nc = ncol & 15;
            uint32_t db = (uint32_t)(nhalf * 16384 + k * 256 + ((nc ^ (k & 7)) << 4));
            size_t src = (size_t)(c * 64 + k) * 256 + nhalf * 128 + nc * 8;
            cp16(s0 + 16384 + db, Bgh + src);
            cp16(s0 + 49152 + db, Bgl + src);
        }
        CP_COMMIT();
    };

    float acc[4][8][4];
#pragma unroll
    for (int i = 0; i < 4; i++)
#pragma unroll
        for (int j = 0; j < 8; j++)
#pragma unroll
            for (int q = 0; q < 4; q++) acc[i][j][q] = 0.f;

    const int wm = (wid & 1) * 64;
    const int wng = (wid >> 1) * 64;
    const uint32_t nhb = (uint32_t)((wng >> 7) * 16384);
    const int ncb = (wng & 127) >> 3;

    auto compute = [&](uint32_t s0) {
        uint32_t sa = s0, sbh = s0 + 16384, sbl = s0 + 49152;
#pragma unroll
        for (int kq = 0; kq < 4; kq++) {
            uint32_t ar[4][4], bh[4][4], bl[4][4];
#pragma unroll
            for (int mi = 0; mi < 4; mi++) {
                int m = wm + mi * 16 + (lane & 15);
                int kcc = kq * 2 + (lane >> 4);
                uint32_t ad = (uint32_t)(m * 128 + ((kcc ^ (m & 7)) << 4));
                LDSM4(ar[mi][0], ar[mi][1], ar[mi][2], ar[mi][3], sa + ad);
            }
#pragma unroll
            for (int nj = 0; nj < 4; nj++) {
                int kr = kq * 16 + (lane & 15);
                int nc = ncb + nj * 2 + (lane >> 4);
                uint32_t bd = nhb + (uint32_t)(kr * 256 + ((nc ^ (kr & 7)) << 4));
                LDSM4T(bh[nj][0], bh[nj][1], bh[nj][2], bh[nj][3], sbh + bd);
                LDSM4T(bl[nj][0], bl[nj][1], bl[nj][2], bl[nj][3], sbl + bd);
            }
#pragma unroll
            for (int mi = 0; mi < 4; mi++)
#pragma unroll
                for (int nt = 0; nt < 8; nt++) {
                    int nj = nt >> 1, pq = (nt & 1) * 2;
                    MMA_F16(acc[mi][nt], ar[mi], bh[nj][pq], bh[nj][pq + 1]);
                    MMA_F16(acc[mi][nt], ar[mi], bl[nj][pq], bl[nj][pq + 1]);
                }
        }
    };

    load_chunk(0, 0);
    for (int ch = 0; ch < 8; ch++) {
        if (ch < 7) { load_chunk(ch + 1, (ch + 1) & 1); CP_WAIT(1); }
        else        { CP_WAIT(0); }
        __syncthreads();
        compute(sb + (ch & 1) * STAGE);
        __syncthreads();
    }

    // ---- epilogue: fp32 stats from accs, store h as fp16 ----
    float s = 0.f, ss = 0.f;
    int rbase = T * 128 + wm + (lane >> 2);
    int cbase = wng + (lane & 3) * 2;
#pragma unroll
    for (int mi = 0; mi < 4; mi++) {
        int r0 = rbase + mi * 16;
        int r1 = r0 + 8;
        bool v0 = r0 < nvalid, v1 = r1 < nvalid;
#pragma unroll
        for (int nt = 0; nt < 8; nt++) {
            int col = cbase + nt * 8;
            if (v0) {
                float px = acc[mi][nt][0], py = acc[mi][nt][1];
                *(__half2*)&g_h16[(size_t)r0 * DH + col] = __floats2half2_rn(px, py);
                s += px + py; ss += px * px + py * py;
            }
            if (v1) {
                float px = acc[mi][nt][2], py = acc[mi][nt][3];
                *(__half2*)&g_h16[(size_t)r1 * DH + col] = __floats2half2_rn(px, py);
                s += px + py; ss += px * px + py * py;
            }
        }
    }
    __syncthreads();
    float* red = (float*)smem;
    red[tid] = s; red[256 + tid] = ss;
    __syncthreads();
    for (int o = 128; o > 0; o >>= 1) {
        if (tid < o) { red[tid] += red[tid + o]; red[256 + tid] += red[256 + tid + o]; }
        __syncthreads();
    }
    if (tid == 0) { g_part[T] = red[0]; g_part2[T] = red[256]; }
}

// ---------------- lin1: fp16 2-pass, 128m x 256n, K=128 (2x64) -> g_hn + g_a[.,256:] ----------------
__global__ __launch_bounds__(256, 1) void k_lin1(const float* __restrict__ bias, int nvalid) {
    extern __shared__ char smem[];
    uint32_t sb = s2u(smem);
    const int tid = threadIdx.x, lane = tid & 31, wid = tid >> 5;
    const int T = blockIdx.x;

    auto load_chunk = [&](int c, int st) {
        uint32_t s0 = sb + st * STAGE;
#pragma unroll
        for (int i = 0; i < 4; i++) {
            int e = tid + i * 256;
            int m = e >> 3, kc = e & 7;
            uint32_t da = (uint32_t)(m * 128 + ((kc ^ (m & 7)) << 4));
            cp16(s0 + da, g_x16 + (size_t)(T * 128 + m) * 128 + c * 64 + kc * 8);
        }
#pragma unroll
        for (int i = 0; i < 8; i++) {
            int e = tid + i * 256;
            int k = e >> 5, ncol = e & 31;
            int nhalf = ncol >> 4, nc = ncol & 15;
            uint32_t db = (uint32_t)(nhalf * 16384 + k * 256 + ((nc ^ (k & 7)) << 4));
            size_t src = (size_t)(c * 64 + k) * 256 + nhalf * 128 + nc * 8;
            cp16(s0 + 16384 + db, g_w1h + src);
            cp16(s0 + 49152 + db, g_w1l + src);
        }
        CP_COMMIT();
    };

    float acc[4][8][4];
#pragma unroll
    for (int i = 0; i < 4; i++)
#pragma unroll
        for (int j = 0; j < 8; j++)
#pragma unroll
            for (int q = 0; q < 4; q++) acc[i][j][q] = 0.f;

    const int wm = (wid & 1) * 64;
    const int wng = (wid >> 1) * 64;
    const uint32_t nhb = (uint32_t)((wng >> 7) * 16384);
    const int ncb = (wng & 127) >> 3;

    auto compute = [&](uint32_t s0) {
        uint32_t sa = s0, sbh = s0 + 16384, sbl = s0 + 49152;
#pragma unroll
        for (int kq = 0; kq < 4; kq++) {
            uint32_t ar[4][4], bh[4][4], bl[4][4];
#pragma unroll
            for (int mi = 0; mi < 4; mi++) {
                int m = wm + mi * 16 + (lane & 15);
                int kcc = kq * 2 + (lane >> 4);
                uint32_t ad = (uint32_t)(m * 128 + ((kcc ^ (m & 7)) << 4));
                LDSM4(ar[mi][0], ar[mi][1], ar[mi][2], ar[mi][3], sa + ad);
            }
#pragma unroll
            for (int nj = 0; nj < 4; nj++) {
                int kr = kq * 16 + (lane & 15);
                int nc = ncb + nj * 2 + (lane >> 4);
                uint32_t bd = nhb + (uint32_t)(kr * 256 + ((nc ^ (kr & 7)) << 4));
                LDSM4T(bh[nj][0], bh[nj][1], bh[nj][2], bh[nj][3], sbh + bd);
                LDSM4T(bl[nj][0], bl[nj][1], bl[nj][2], bl[nj][3], sbl + bd);
            }
#pragma unroll
            for (int mi = 0; mi < 4; mi++)
#pragma unroll
                for (int nt = 0; nt < 8; nt++) {
                    int nj = nt >> 1, pq = (nt & 1) * 2;
                    MMA_F16(acc[mi][nt], ar[mi], bh[nj][pq], bh[nj][pq + 1]);
                    MMA_F16(acc[mi][nt], ar[mi], bl[nj][pq], bl[nj][pq + 1]);
                }
        }
    };

    load_chunk(0, 0);
    load_chunk(1, 1);
    CP_WAIT(1);
    __syncthreads();
    compute(sb);
    __syncthreads();
    CP_WAIT(0);
    __syncthreads();
    compute(sb + STAGE);

    int rbase = T * 128 + wm + (lane >> 2);
    int cbase = wng + (lane & 3) * 2;
#pragma unroll
    for (int mi = 0; mi < 4; mi++) {
        int r0 = rbase + mi * 16;
        int r1 = r0 + 8;
#pragma unroll
        for (int nt = 0; nt < 8; nt++) {
            int col = cbase + nt * 8;
            float2 bb = *(const float2*)&bias[col];
            float v0 = fmaxf(acc[mi][nt][0] + bb.x, 0.f);
            float v1 = fmaxf(acc[mi][nt][1] + bb.y, 0.f);
            __half2 h01 = __floats2half2_rn(v0, v1);
            *(__half2*)&g_a[(size_t)r0 * 512 + 256 + col] = h01;
            if (r0 < nvalid) *(__half2*)&g_hn[(size_t)r0 * DH + col] = h01;
            float v2 = fmaxf(acc[mi][nt][2] + bb.x, 0.f);
            float v3 = fmaxf(acc[mi][nt][3] + bb.y, 0.f);
            __half2 h23 = __floats2half2_rn(v2, v3);
            *(__half2*)&g_a[(size_t)r1 * 512 + 256 + col] = h23;
            if (r1 < nvalid) *(__half2*)&g_hn[(size_t)r1 * DH + col] = h23;
        }
    }
}

// ---------------- lin2: fp16 2-pass, 256m x 128n, K=256 (4x64) ----------------
#define L2STAGE 65536u
#define L2SMTOT 131072
__global__ __launch_bounds__(256, 1) void k_lin2(const float* __restrict__ bias,
                                                 float* __restrict__ out, int nvalid) {
    extern __shared__ char smem[];
    uint32_t sb = s2u(smem);
    const int tid = threadIdx.x, lane = tid & 31, wid = tid >> 5;
    const int T = blockIdx.x;

    auto load_chunk = [&](int c, int st) {
        uint32_t s0 = sb + st * L2STAGE;
#pragma unroll
        for (int i = 0; i < 8; i++) {
            int e = tid + i * 256;
            int m = e >> 3, kc = e & 7;
            uint32_t da = (uint32_t)(m * 128 + ((kc ^ (m & 7)) << 4));
            cp16(s0 + da, g_hn + (size_t)(T * 256 + m) * DH + c * 64 + kc * 8);
        }
#pragma unroll
        for (int i = 0; i < 4; i++) {
            int e = tid + i * 256;
            int k = e >> 4, nc = e & 15;
            uint32_t db = (uint32_t)(k * 256 + ((nc ^ (k & 7)) << 4));
            size_t src = (size_t)(c * 64 + k) * 128 + nc * 8;
            cp16(s0 + 32768 + db, g_w2h + src);
            cp16(s0 + 49152 + db, g_w2l + src);
        }
        CP_COMMIT();
    };

    float acc[4][8][4];
#pragma unroll
    for (int i = 0; i < 4; i++)
#pragma unroll
        for (int j = 0; j < 8; j++)
#pragma unroll
            for (int q = 0; q < 4; q++) acc[i][j][q] = 0.f;

    const int wm = (wid & 3) * 64;
    const int wn = (wid >> 2) * 64;
    const int ncb = wn >> 3;

    auto compute = [&](uint32_t s0) {
        uint32_t sa = s0, sbh = s0 + 32768, sbl = s0 + 49152;
#pragma unroll
        for (int kq = 0; kq < 4; kq++) {
            uint32_t ar[4][4], bh[4][4], bl[4][4];
#pragma unroll
            for (int mi = 0; mi < 4; mi++) {
                int m = wm + mi * 16 + (lane & 15);
                int kcc = kq * 2 + (lane >> 4);
                uint32_t ad = (uint32_t)(m * 128 + ((kcc ^ (m & 7)) << 4));
                LDSM4(ar[mi][0], ar[mi][1], ar[mi][2], ar[mi][3], sa + ad);
            }
#pragma unroll
            for (int nj = 0; nj < 4; nj++) {
                int kr = kq * 16 + (lane & 15);
                int nc = ncb + nj * 2 + (lane >> 4);
                uint32_t bd = (uint32_t)(kr * 256 + ((nc ^ (kr & 7)) << 4));
                LDSM4T(bh[nj][0], bh[nj][1], bh[nj][2], bh[nj][3], sbh + bd);
                LDSM4T(bl[nj][0], bl[nj][1], bl[nj][2], bl[nj][3], sbl + bd);
            }
#pragma unroll
            for (int mi = 0; mi < 4; mi++)
#pragma unroll
                for (int nt = 0; nt < 8; nt++) {
                    int nj = nt >> 1, pq = (nt & 1) * 2;
                    MMA_F16(acc[mi][nt], ar[mi], bh[nj][pq], bh[nj][pq + 1]);
                    MMA_F16(acc[mi][nt], ar[mi], bl[nj][pq], bl[nj][pq + 1]);
                }
        }
    };

    load_chunk(0, 0);
    for (int ch = 0; ch < 4; ch++) {
        if (ch < 3) { load_chunk(ch + 1, (ch + 1) & 1); CP_WAIT(1); }
        else        { CP_WAIT(0); }
        __syncthreads();
        compute(sb + (ch & 1) * L2STAGE);
        __syncthreads();
    }

    int rbase = T * 256 + wm + (lane >> 2);
    int cbase = wn + (lane & 3) * 2;
#pragma unroll
    for (int mi = 0; mi < 4; mi++) {
        int r0 = rbase + mi * 16;
        int r1 = r0 + 8;
        bool v0 = r0 < nvalid, v1 = r1 < nvalid;
#pragma unroll
        for (int nt = 0; nt < 8; nt++) {
            int col = cbase + nt * 8;
            float2 bb = *(const float2*)&bias[col];
            if (v0) {
                float2 p = make_float2(fmaxf(acc[mi][nt][0] + bb.x, 0.f),
                                       fmaxf(acc[mi][nt][1] + bb.y, 0.f));
                *(float2*)&out[(size_t)r0 * 128 + col] = p;
            }
            if (v1) {
                float2 p = make_float2(fmaxf(acc[mi][nt][2] + bb.x, 0.f),
                                       fmaxf(acc[mi][nt][3] + bb.y, 0.f));
                *(float2*)&out[(size_t)r1 * 128 + col] = p;
            }
        }
    }
}

// ---------------- layernorm: finalize + normalize+relu, fp16 g_h16 -> fp16 g_hn ----------------
__global__ __launch_bounds__(256) void k_norm(const float* __restrict__ gamma,
                                              const float* __restrict__ beta,
                                              int total8, int nparts, float invcnt) {
    __shared__ float sred[512];
    __shared__ float s_scale[256], s_shift[256];
    const int tid = threadIdx.x;

    float s = 0.f, ss = 0.f;
    for (int i = tid; i < nparts; i += 256) { s += g_part[i]; ss += g_part2[i]; }
    sred[tid] = s; sred[256 + tid] = ss;
    __syncthreads();
    for (int o = 128; o > 0; o >>= 1) {
        if (tid < o) { sred[tid] += sred[tid + o]; sred[256 + tid] += sred[256 + tid + o]; }
        __syncthreads();
    }
    float mu = sred[0] * invcnt;
    float var = fmaxf(sred[256] * invcnt - mu * mu, 0.f);
    float inv = 1.0f / (sqrtf(var) + 1e-5f);
    float gch = gamma[tid] * inv;
    s_scale[tid] = gch;
    s_shift[tid] = beta[tid] - mu * gch;
    __syncthreads();

    int stride = gridDim.x * 256;
    for (int i = blockIdx.x * 256 + tid; i < total8; i += stride) {
        uint4 v = ((const uint4*)g_h16)[i];
        const __half2* ph = (const __half2*)&v;
        int f = (i * 8) & 255;
        uint4 o;
        __half2* po = (__half2*)&o;
#pragma unroll
        for (int j = 0; j < 4; j++) {
            float2 hv = __half22float2(ph[j]);
            float2 sc = *(const float2*)&s_scale[f + 2 * j];
            float2 sh = *(const float2*)&s_shift[f + 2 * j];
            float a = fmaxf(fmaf(hv.x, sc.x, sh.x), 0.f);
            float b = fmaxf(fmaf(hv.y, sc.y, sh.y), 0.f);
            po[j] = __floats2half2_rn(a, b);
        }
        ((uint4*)g_hn)[i] = o;
    }
}

// ---------------- launch ----------------
extern "C" void kernel_launch(void* const* d_in, const int* in_sizes, int n_in,
                              void* d_out, int out_size) {
    const float* x      = (const float*)d_in[0];
    const int*   ei     = (const int*)d_in[1];
    const float* lin1_w = (const float*)d_in[2];
    const float* lin1_b = (const float*)d_in[3];
    const float* w1     = (const float*)d_in[4];
    const float* w2     = (const float*)d_in[5];
    const float* gamma  = (const float*)d_in[6];
    const float* betab  = (const float*)d_in[7];
    const float* lin2_w = (const float*)d_in[8];
    const float* lin2_b = (const float*)d_in[9];
    float* out = (float*)d_out;

    int N = in_sizes[0] / 128;
    int E = in_sizes[1] / 2;
    const int* row = ei;
    const int* col = ei + E;

    int Mt = (N + 127) / 128;
    int Mt2 = (N + 255) / 256;
    int total8 = N * (DH / 8);
    float invcnt = 1.0f / ((float)N * (float)DH);

    static int smem_set = 0;
    if (!smem_set) {
        cudaFuncSetAttribute(k_mma, cudaFuncAttributeMaxDynamicSharedMemorySize, SMTOT);
        cudaFuncSetAttribute(k_lin1, cudaFuncAttributeMaxDynamicSharedMemorySize, SMTOT);
        cudaFuncSetAttribute(k_lin2, cudaFuncAttributeMaxDynamicSharedMemorySize, L2SMTOT);
        smem_set = 1;
    }

    k_init<<<(N + 255) / 256, 256>>>(N);
    k_count<<<(E + 255) / 256, 256>>>(col, E);
    k_scan<<<1, 1024>>>(N, E);
    k_scatter<<<(E + 255) / 256, 256>>>(row, col, E);
    k_prep_b<<<(NL * 512 * 256 + 255) / 256, 256>>>(w1, w2);
    k_prep_x<<<(N * 128 + 255) / 256, 256>>>(x, N * 128);
    k_prep_w<<<(2 * 128 * 256 + 255) / 256, 256>>>(lin1_w, lin2_w);

    // x0 = relu(x @ lin1_w + b) -> g_hn + g_a upper-k (tensor path)
    k_lin1<<<Mt, 256, SMTOT>>>(lin1_b, N);

    for (int l = 0; l < NL; l++) {
        k_gather<<<(N * 32 + 255) / 256, 256>>>(N);
        k_mma<<<Mt, 256, SMTOT>>>(l, N);
        k_norm<<<1184, 256>>>(gamma + l * DH, betab + l * DH, total8, Mt, invcnt);
    }

    // out = relu(norm7(h) @ lin2_w + b)
    k_lin2<<<Mt2, 256, L2SMTOT>>>(lin2_b, out, N);
}

// round 14
// speedup vs baseline: 1.0386x; 1.0386x over previous
#include <cuda_runtime.h>
#include <cuda_fp16.h>
#include <math.h>
#include <stdint.h>

#define NN 50000
#define EE 800000
#define DH 256
#define NL 8
#define NTILES ((NN + 127) / 128)        // 391
#define NPAD (NTILES * 128)              // 50048
#define NT2 ((NN + 255) / 256)           // 196
#define NPAD2 (NT2 * 256)                // 50176

// ---------------- scratch ----------------
__device__ float g_ha[NN * DH];                                  // fp32 h_out (per-layer)
__device__ __align__(16) __half g_hn[(size_t)NPAD2 * DH];        // fp16 dis*relu(norm(h)) / dis*x0 (unscaled for last layer)
__device__ __align__(16) __half g_a[(size_t)NPAD * 512];         // fp16 A [node][k] k<256 agg, k>=256 x0
__device__ __align__(16) __half g_bh[(size_t)NL * 512 * 256];    // B' hi
__device__ __align__(16) __half g_bl[(size_t)NL * 512 * 256];    // B' lo
__device__ __align__(16) __half g_x16[(size_t)NPAD * 128];       // fp16 x
__device__ __align__(16) __half g_w1h[128 * 256], g_w1l[128 * 256];
__device__ __align__(16) __half g_w2h[256 * 128], g_w2l[256 * 128];
__device__ float g_dis[NN];
__device__ int   g_counts[NN];
__device__ int   g_cursor[NN];
__device__ int   g_rowptr[NN + 1];
__device__ int   g_csr[EE];
__device__ float g_part[NTILES + 8];
__device__ float g_part2[NTILES + 8];

// ---------------- helpers ----------------
__device__ __forceinline__ uint32_t s2u(const void* p) {
    uint32_t a;
    asm("{ .reg .u64 t; cvta.to.shared.u64 t, %1; cvt.u32.u64 %0, t; }" : "=r"(a) : "l"(p));
    return a;
}
__device__ __forceinline__ void cp16(uint32_t dst, const void* src) {
    asm volatile("cp.async.cg.shared.global [%0], [%1], 16;" :: "r"(dst), "l"(src) : "memory");
}
#define CP_COMMIT() asm volatile("cp.async.commit_group;" ::: "memory")
#define CP_WAIT(n)  asm volatile("cp.async.wait_group %0;" :: "n"(n) : "memory")

#define LDSM4(r0,r1,r2,r3,a) \
    asm volatile("ldmatrix.sync.aligned.m8n8.x4.shared.b16 {%0,%1,%2,%3}, [%4];" \
                 : "=r"(r0),"=r"(r1),"=r"(r2),"=r"(r3) : "r"(a))
#define LDSM4T(r0,r1,r2,r3,a) \
    asm volatile("ldmatrix.sync.aligned.m8n8.x4.trans.shared.b16 {%0,%1,%2,%3}, [%4];" \
                 : "=r"(r0),"=r"(r1),"=r"(r2),"=r"(r3) : "r"(a))
#define MMA_F16(c,a,b0,b1) \
    asm volatile("mma.sync.aligned.m16n8k16.row.col.f32.f16.f16.f32 " \
                 "{%0,%1,%2,%3}, {%4,%5,%6,%7}, {%8,%9}, {%0,%1,%2,%3};" \
                 : "+f"((c)[0]),"+f"((c)[1]),"+f"((c)[2]),"+f"((c)[3]) \
                 : "r"((a)[0]),"r"((a)[1]),"r"((a)[2]),"r"((a)[3]),"r"(b0),"r"(b1))

__device__ __forceinline__ void split_h(float v, __half& h, __half& l) {
    h = __float2half_rn(v);
    l = __float2half_rn(v - __half2float(h));
}

// ---------------- graph preprocessing ----------------
__global__ void k_init(int n) {
    int i = blockIdx.x * blockDim.x + threadIdx.x;
    if (i < n) { g_counts[i] = 0; g_cursor[i] = 0; }
}
__global__ void k_count(const int* __restrict__ col, int E) {
    int e = blockIdx.x * blockDim.x + threadIdx.x;
    if (e < E) atomicAdd(&g_counts[col[e]], 1);
}
__global__ void k_scan(int n, int E) {
    __shared__ int sh[1024];
    int tid = threadIdx.x;
    int C = (n + 1023) >> 10;
    int base = tid * C;
    int s = 0;
    for (int i = 0; i < C; i++) { int idx = base + i; if (idx < n) s += g_counts[idx]; }
    sh[tid] = s; __syncthreads();
    for (int off = 1; off < 1024; off <<= 1) {
        int v = (tid >= off) ? sh[tid - off] : 0;
        __syncthreads();
        sh[tid] += v;
        __syncthreads();
    }
    int run = (tid > 0) ? sh[tid - 1] : 0;
    for (int i = 0; i < C; i++) {
        int idx = base + i;
        if (idx < n) {
            g_rowptr[idx] = run;
            int c = g_counts[idx];
            run += c;
            g_dis[idx] = rsqrtf((float)(c + 1));
        }
    }
    if (tid == 0) g_rowptr[n] = E;
}
__global__ void k_scatter(const int* __restrict__ row, const int* __restrict__ col, int E) {
    int e = blockIdx.x * blockDim.x + threadIdx.x;
    if (e < E) {
        int c = col[e];
        int p = g_rowptr[c] + atomicAdd(&g_cursor[c], 1);
        g_csr[p] = row[e];
    }
}

// ---------------- weight / input prep ----------------
__global__ void k_prep_b(const float* __restrict__ w1, const float* __restrict__ w2) {
    int idx = blockIdx.x * blockDim.x + threadIdx.x;
    if (idx >= NL * 512 * 256) return;
    int n = idx & 255;
    int k = (idx >> 8) & 511;
    int l = idx >> 17;
    float beta = logf(1.0f / (float)(l + 1) + 1.0f);
    float v = (k < 256) ? w1[(l << 16) + (k << 8) + n]
                        : w2[(l << 16) + ((k - 256) << 8) + n];
    float val = 0.5f * beta * v;
    if (k == n || k == n + 256) val += 0.5f * (1.0f - beta);
    split_h(val, g_bh[idx], g_bl[idx]);
}
__global__ void k_prep_x(const float* __restrict__ x, int total) {
    int i = blockIdx.x * blockDim.x + threadIdx.x;
    if (i < total) g_x16[i] = __float2half_rn(x[i]);
}
__global__ void k_prep_w(const float* __restrict__ w1, const float* __restrict__ w2) {
    int i = blockIdx.x * blockDim.x + threadIdx.x;
    if (i < 128 * 256) {
        split_h(w1[i], g_w1h[i], g_w1l[i]);
    } else if (i < 128 * 256 + 256 * 128) {
        int j = i - 128 * 256;
        split_h(w2[j], g_w2h[j], g_w2l[j]);
    }
}

// ---------------- CSR gather (dis pre-folded into g_hn) -> fp16 A rows (k 0..255) ----------------
__global__ __launch_bounds__(256) void k_gather(int n) {
    int w = (blockIdx.x * blockDim.x + threadIdx.x) >> 5;
    int lane = threadIdx.x & 31;
    if (w >= n) return;
    const uint4* __restrict__ hn = (const uint4*)g_hn;
    float dc = g_dis[w];
    float a[8];
    {
        uint4 v = hn[w * 32 + lane];          // already dis_w-scaled
        const __half2* ph = (const __half2*)&v;
#pragma unroll
        for (int j = 0; j < 4; j++) {
            float2 f = __half22float2(ph[j]);
            a[2 * j] = f.x; a[2 * j + 1] = f.y;
        }
    }
    int beg = g_rowptr[w], end = g_rowptr[w + 1];
    int i = beg;
    for (; i + 3 < end; i += 4) {
        int s0 = g_csr[i], s1 = g_csr[i + 1], s2 = g_csr[i + 2], s3 = g_csr[i + 3];
        uint4 p = hn[s0 * 32 + lane], q = hn[s1 * 32 + lane];
        uint4 r = hn[s2 * 32 + lane], t = hn[s3 * 32 + lane];
        const __half2* pp = (const __half2*)&p;
        const __half2* qq = (const __half2*)&q;
        const __half2* rr = (const __half2*)&r;
        const __half2* tt = (const __half2*)&t;
#pragma unroll
        for (int j = 0; j < 4; j++) {
            float2 fp = __half22float2(pp[j]);
            float2 fq = __half22float2(qq[j]);
            float2 fr = __half22float2(rr[j]);
            float2 ft = __half22float2(tt[j]);
            a[2 * j]     += (fp.x + fq.x) + (fr.x + ft.x);
            a[2 * j + 1] += (fp.y + fq.y) + (fr.y + ft.y);
        }
    }
    for (; i < end; i++) {
        int s0 = g_csr[i];
        uint4 p = hn[s0 * 32 + lane];
        const __half2* pp = (const __half2*)&p;
#pragma unroll
        for (int j = 0; j < 4; j++) {
            float2 fp = __half22float2(pp[j]);
            a[2 * j]     += fp.x;
            a[2 * j + 1] += fp.y;
        }
    }
    size_t ro = (size_t)w * 512 + lane * 8;
    __half hh[8];
#pragma unroll
    for (int j = 0; j < 8; j++) hh[j] = __float2half_rn(a[j] * dc);
    *(uint4*)&g_a[ro] = *(uint4*)hh;
}

// ---------------- layer GEMM: fp16 2-pass, 128m x 256n, K=512 (8x64) ----------------
#define STAGE 81920u
#define SMTOT 163840
__global__ __launch_bounds__(256, 1) void k_mma(int layer, int nvalid) {
    extern __shared__ char smem[];
    uint32_t sb = s2u(smem);
    const int tid = threadIdx.x, lane = tid & 31, wid = tid >> 5;
    const int T = blockIdx.x;

    const __half* __restrict__ Ag = g_a + (size_t)T * 128 * 512;
    const __half* __restrict__ Bgh = g_bh + (size_t)layer * 512 * 256;
    const __half* __restrict__ Bgl = g_bl + (size_t)layer * 512 * 256;

    auto load_chunk = [&](int c, int st) {
        uint32_t s0 = sb + st * STAGE;
#pragma unroll
        for (int i = 0; i < 4; i++) {
            int e = tid + i * 256;
            int m = e >> 3, kc = e & 7;
            uint32_t da = (uint32_t)(m * 128 + ((kc ^ (m & 7)) << 4));
            cp16(s0 + da, Ag + (size_t)m * 512 + c * 64 + kc * 8);
        }
#pragma unroll
        for (int i = 0; i < 8; i++) {
            int e = tid + i * 256;
            int k = e >> 5, ncol = e & 31;
            int nhalf = ncol >> 4, nc = ncol & 15;
            uint32_t db = (uint32_t)(nhalf * 16384 + k * 256 + ((nc ^ (k & 7)) << 4));
            size_t src = (size_t)(c * 64 + k) * 256 + nhalf * 128 + nc * 8;
            cp16(s0 + 16384 + db, Bgh + src);
            cp16(s0 + 49152 + db, Bgl + src);
        }
        CP_COMMIT();
    };

    float acc[4][8][4];
#pragma unroll
    for (int i = 0; i < 4; i++)
#pragma unroll
        for (int j = 0; j < 8; j++)
#pragma unroll
            for (int q = 0; q < 4; q++) acc[i][j][q] = 0.f;

    const int wm = (wid & 1) * 64;
    const int wng = (wid >> 1) * 64;
    const uint32_t nhb = (uint32_t)((wng >> 7) * 16384);
    const int ncb = (wng & 127) >> 3;

    auto compute = [&](uint32_t s0) {
        uint32_t sa = s0, sbh = s0 + 16384, sbl = s0 + 49152;
#pragma unroll
        for (int kq = 0; kq < 4; kq++) {
            uint32_t ar[4][4], bh[4][4], bl[4][4];
#pragma unroll
            for (int mi = 0; mi < 4; mi++) {
                int m = wm + mi * 16 + (lane & 15);
                int kcc = kq * 2 + (lane >> 4);
                uint32_t ad = (uint32_t)(m * 128 + ((kcc ^ (m & 7)) << 4));
                LDSM4(ar[mi][0], ar[mi][1], ar[mi][2], ar[mi][3], sa + ad);
            }
#pragma unroll
            for (int nj = 0; nj < 4; nj++) {
                int kr = kq * 16 + (lane & 15);
                int nc = ncb + nj * 2 + (lane >> 4);
                uint32_t bd = nhb + (uint32_t)(kr * 256 + ((nc ^ (kr & 7)) << 4));
                LDSM4T(bh[nj][0], bh[nj][1], bh[nj][2], bh[nj][3], sbh + bd);
                LDSM4T(bl[nj][0], bl[nj][1], bl[nj][2], bl[nj][3], sbl + bd);
            }
#pragma unroll
            for (int mi = 0; mi < 4; mi++)
#pragma unroll
                for (int nt = 0; nt < 8; nt++) {
                    int nj = nt >> 1, pq = (nt & 1) * 2;
                    MMA_F16(acc[mi][nt], ar[mi], bh[nj][pq], bh[nj][pq + 1]);
                    MMA_F16(acc[mi][nt], ar[mi], bl[nj][pq], bl[nj][pq + 1]);
                }
        }
    };

    load_chunk(0, 0);
    for (int ch = 0; ch < 8; ch++) {
        if (ch < 7) { load_chunk(ch + 1, (ch + 1) & 1); CP_WAIT(1); }
        else        { CP_WAIT(0); }
        __syncthreads();
        compute(sb + (ch & 1) * STAGE);
        __syncthreads();
    }

    float s = 0.f, ss = 0.f;
    int rbase = T * 128 + wm + (lane >> 2);
    int cbase = wng + (lane & 3) * 2;
#pragma unroll
    for (int mi = 0; mi < 4; mi++) {
        int r0 = rbase + mi * 16;
        int r1 = r0 + 8;
        bool v0 = r0 < nvalid, v1 = r1 < nvalid;
#pragma unroll
        for (int nt = 0; nt < 8; nt++) {
            int col = cbase + nt * 8;
            if (v0) {
                float2 p = make_float2(acc[mi][nt][0], acc[mi][nt][1]);
                *(float2*)&g_ha[(size_t)r0 * DH + col] = p;
                s += p.x + p.y; ss += p.x * p.x + p.y * p.y;
            }
            if (v1) {
                float2 p = make_float2(acc[mi][nt][2], acc[mi][nt][3]);
                *(float2*)&g_ha[(size_t)r1 * DH + col] = p;
                s += p.x + p.y; ss += p.x * p.x + p.y * p.y;
            }
        }
    }
    __syncthreads();
    float* red = (float*)smem;
    red[tid] = s; red[256 + tid] = ss;
    __syncthreads();
    for (int o = 128; o > 0; o >>= 1) {
        if (tid < o) { red[tid] += red[tid + o]; red[256 + tid] += red[256 + tid + o]; }
        __syncthreads();
    }
    if (tid == 0) { g_part[T] = red[0]; g_part2[T] = red[256]; }
}

// ---------------- lin1: fp16 2-pass, 128m x 256n, K=128 (2x64) -> dis*x0 in g_hn + x0 in g_a ----------------
__global__ __launch_bounds__(256, 1) void k_lin1(const float* __restrict__ bias, int nvalid) {
    extern __shared__ char smem[];
    uint32_t sb = s2u(smem);
    const int tid = threadIdx.x, lane = tid & 31, wid = tid >> 5;
    const int T = blockIdx.x;

    auto load_chunk = [&](int c, int st) {
        uint32_t s0 = sb + st * STAGE;
#pragma unroll
        for (int i = 0; i < 4; i++) {
            int e = tid + i * 256;
            int m = e >> 3, kc = e & 7;
            uint32_t da = (uint32_t)(m * 128 + ((kc ^ (m & 7)) << 4));
            cp16(s0 + da, g_x16 + (size_t)(T * 128 + m) * 128 + c * 64 + kc * 8);
        }
#pragma unroll
        for (int i = 0; i < 8; i++) {
            int e = tid + i * 256;
            int k = e >> 5, ncol = e & 31;
            int nhalf = ncol >> 4, nc = ncol & 15;
            uint32_t db = (uint32_t)(nhalf * 16384 + k * 256 + ((nc ^ (k & 7)) << 4));
            size_t src = (size_t)(c * 64 + k) * 256 + nhalf * 128 + nc * 8;
            cp16(s0 + 16384 + db, g_w1h + src);
            cp16(s0 + 49152 + db, g_w1l + src);
        }
        CP_COMMIT();
    };

    float acc[4][8][4];
#pragma unroll
    for (int i = 0; i < 4; i++)
#pragma unroll
        for (int j = 0; j < 8; j++)
#pragma unroll
            for (int q = 0; q < 4; q++) acc[i][j][q] = 0.f;

    const int wm = (wid & 1) * 64;
    const int wng = (wid >> 1) * 64;
    const uint32_t nhb = (uint32_t)((wng >> 7) * 16384);
    const int ncb = (wng & 127) >> 3;

    auto compute = [&](uint32_t s0) {
        uint32_t sa = s0, sbh = s0 + 16384, sbl = s0 + 49152;
#pragma unroll
        for (int kq = 0; kq < 4; kq++) {
            uint32_t ar[4][4], bh[4][4], bl[4][4];
#pragma unroll
            for (int mi = 0; mi < 4; mi++) {
                int m = wm + mi * 16 + (lane & 15);
                int kcc = kq * 2 + (lane >> 4);
                uint32_t ad = (uint32_t)(m * 128 + ((kcc ^ (m & 7)) << 4));
                LDSM4(ar[mi][0], ar[mi][1], ar[mi][2], ar[mi][3], sa + ad);
            }
#pragma unroll
            for (int nj = 0; nj < 4; nj++) {
                int kr = kq * 16 + (lane & 15);
                int nc = ncb + nj * 2 + (lane >> 4);
                uint32_t bd = nhb + (uint32_t)(kr * 256 + ((nc ^ (kr & 7)) << 4));
                LDSM4T(bh[nj][0], bh[nj][1], bh[nj][2], bh[nj][3], sbh + bd);
                LDSM4T(bl[nj][0], bl[nj][1], bl[nj][2], bl[nj][3], sbl + bd);
            }
#pragma unroll
            for (int mi = 0; mi < 4; mi++)
#pragma unroll
                for (int nt = 0; nt < 8; nt++) {
                    int nj = nt >> 1, pq = (nt & 1) * 2;
                    MMA_F16(acc[mi][nt], ar[mi], bh[nj][pq], bh[nj][pq + 1]);
                    MMA_F16(acc[mi][nt], ar[mi], bl[nj][pq], bl[nj][pq + 1]);
                }
        }
    };

    load_chunk(0, 0);
    load_chunk(1, 1);
    CP_WAIT(1);
    __syncthreads();
    compute(sb);
    __syncthreads();
    CP_WAIT(0);
    __syncthreads();
    compute(sb + STAGE);

    int rbase = T * 128 + wm + (lane >> 2);
    int cbase = wng + (lane & 3) * 2;
#pragma unroll
    for (int mi = 0; mi < 4; mi++) {
        int r0 = rbase + mi * 16;
        int r1 = r0 + 8;
        float d0 = (r0 < nvalid) ? g_dis[r0] : 0.f;
        float d1 = (r1 < nvalid) ? g_dis[r1] : 0.f;
#pragma unroll
        for (int nt = 0; nt < 8; nt++) {
            int col = cbase + nt * 8;
            float2 bb = *(const float2*)&bias[col];
            float v0 = fmaxf(acc[mi][nt][0] + bb.x, 0.f);
            float v1 = fmaxf(acc[mi][nt][1] + bb.y, 0.f);
            *(__half2*)&g_a[(size_t)r0 * 512 + 256 + col] = __floats2half2_rn(v0, v1);
            if (r0 < nvalid)
                *(__half2*)&g_hn[(size_t)r0 * DH + col] = __floats2half2_rn(v0 * d0, v1 * d0);
            float v2 = fmaxf(acc[mi][nt][2] + bb.x, 0.f);
            float v3 = fmaxf(acc[mi][nt][3] + bb.y, 0.f);
            *(__half2*)&g_a[(size_t)r1 * 512 + 256 + col] = __floats2half2_rn(v2, v3);
            if (r1 < nvalid)
                *(__half2*)&g_hn[(size_t)r1 * DH + col] = __floats2half2_rn(v2 * d1, v3 * d1);
        }
    }
}

// ---------------- lin2: fp16 2-pass, 256m x 128n, K=256 (4x64) ----------------
#define L2STAGE 65536u
#define L2SMTOT 131072
__global__ __launch_bounds__(256, 1) void k_lin2(const float* __restrict__ bias,
                                                 float* __restrict__ out, int nvalid) {
    extern __shared__ char smem[];
    uint32_t sb = s2u(smem);
    const int tid = threadIdx.x, lane = tid & 31, wid = tid >> 5;
    const int T = blockIdx.x;

    auto load_chunk = [&](int c, int st) {
        uint32_t s0 = sb + st * L2STAGE;
#pragma unroll
        for (int i = 0; i < 8; i++) {
            int e = tid + i * 256;
            int m = e >> 3, kc = e & 7;
            uint32_t da = (uint32_t)(m * 128 + ((kc ^ (m & 7)) << 4));
            cp16(s0 + da, g_hn + (size_t)(T * 256 + m) * DH + c * 64 + kc * 8);
        }
#pragma unroll
        for (int i = 0; i < 4; i++) {
            int e = tid + i * 256;
            int k = e >> 4, nc = e & 15;
            uint32_t db = (uint32_t)(k * 256 + ((nc ^ (k & 7)) << 4));
            size_t src = (size_t)(c * 64 + k) * 128 + nc * 8;
            cp16(s0 + 32768 + db, g_w2h + src);
            cp16(s0 + 49152 + db, g_w2l + src);
        }
        CP_COMMIT();
    };

    float acc[4][8][4];
#pragma unroll
    for (int i = 0; i < 4; i++)
#pragma unroll
        for (int j = 0; j < 8; j++)
#pragma unroll
            for (int q = 0; q < 4; q++) acc[i][j][q] = 0.f;

    const int wm = (wid & 3) * 64;
    const int wn = (wid >> 2) * 64;
    const int ncb = wn >> 3;

    auto compute = [&](uint32_t s0) {
        uint32_t sa = s0, sbh = s0 + 32768, sbl = s0 + 49152;
#pragma unroll
        for (int kq = 0; kq < 4; kq++) {
            uint32_t ar[4][4], bh[4][4], bl[4][4];
#pragma unroll
            for (int mi = 0; mi < 4; mi++) {
                int m = wm + mi * 16 + (lane & 15);
                int kcc = kq * 2 + (lane >> 4);
                uint32_t ad = (uint32_t)(m * 128 + ((kcc ^ (m & 7)) << 4));
                LDSM4(ar[mi][0], ar[mi][1], ar[mi][2], ar[mi][3], sa + ad);
            }
#pragma unroll
            for (int nj = 0; nj < 4; nj++) {
                int kr = kq * 16 + (lane & 15);
                int nc = ncb + nj * 2 + (lane >> 4);
                uint32_t bd = (uint32_t)(kr * 256 + ((nc ^ (kr & 7)) << 4));
                LDSM4T(bh[nj][0], bh[nj][1], bh[nj][2], bh[nj][3], sbh + bd);
                LDSM4T(bl[nj][0], bl[nj][1], bl[nj][2], bl[nj][3], sbl + bd);
            }
#pragma unroll
            for (int mi = 0; mi < 4; mi++)
#pragma unroll
                for (int nt = 0; nt < 8; nt++) {
                    int nj = nt >> 1, pq = (nt & 1) * 2;
                    MMA_F16(acc[mi][nt], ar[mi], bh[nj][pq], bh[nj][pq + 1]);
                    MMA_F16(acc[mi][nt], ar[mi], bl[nj][pq], bl[nj][pq + 1]);
                }
        }
    };

    load_chunk(0, 0);
    for (int ch = 0; ch < 4; ch++) {
        if (ch < 3) { load_chunk(ch + 1, (ch + 1) & 1); CP_WAIT(1); }
        else        { CP_WAIT(0); }
        __syncthreads();
        compute(sb + (ch & 1) * L2STAGE);
        __syncthreads();
    }

    int rbase = T * 256 + wm + (lane >> 2);
    int cbase = wn + (lane & 3) * 2;
#pragma unroll
    for (int mi = 0; mi < 4; mi++) {
        int r0 = rbase + mi * 16;
        int r1 = r0 + 8;
        bool v0 = r0 < nvalid, v1 = r1 < nvalid;
#pragma unroll
        for (int nt = 0; nt < 8; nt++) {
            int col = cbase + nt * 8;
            float2 bb = *(const float2*)&bias[col];
            if (v0) {
                float2 p = make_float2(fmaxf(acc[mi][nt][0] + bb.x, 0.f),
                                       fmaxf(acc[mi][nt][1] + bb.y, 0.f));
                *(float2*)&out[(size_t)r0 * 128 + col] = p;
            }
            if (v1) {
                float2 p = make_float2(fmaxf(acc[mi][nt][2] + bb.x, 0.f),
                                       fmaxf(acc[mi][nt][3] + bb.y, 0.f));
                *(float2*)&out[(size_t)r1 * 128 + col] = p;
            }
        }
    }
}

// ---------------- layernorm: finalize + normalize+relu (+dis prescale), fp32 g_ha -> fp16 g_hn ----------------
__global__ __launch_bounds__(256) void k_norm(const float* __restrict__ gamma,
                                              const float* __restrict__ beta,
                                              int total4, int nparts, float invcnt, int scale_dis) {
    __shared__ float sred[512];
    __shared__ float s_scale[256], s_shift[256];
    const int tid = threadIdx.x;

    float s = 0.f, ss = 0.f;
    for (int i = tid; i < nparts; i += 256) { s += g_part[i]; ss += g_part2[i]; }
    sred[tid] = s; sred[256 + tid] = ss;
    __syncthreads();
    for (int o = 128; o > 0; o >>= 1) {
        if (tid < o) { sred[tid] += sred[tid + o]; sred[256 + tid] += sred[256 + tid + o]; }
        __syncthreads();
    }
    float mu = sred[0] * invcnt;
    float var = fmaxf(sred[256] * invcnt - mu * mu, 0.f);
    float inv = 1.0f / (sqrtf(var) + 1e-5f);
    float gch = gamma[tid] * inv;
    s_scale[tid] = gch;
    s_shift[tid] = beta[tid] - mu * gch;
    __syncthreads();

    int stride = gridDim.x * 256;
    for (int i = blockIdx.x * 256 + tid; i < total4; i += stride) {
        float4 v = ((const float4*)g_ha)[i];
        int f = (i * 4) & 255;
        int node = i >> 6;
        float d = scale_dis ? g_dis[node] : 1.0f;
        float4 g = *(float4*)&s_scale[f];
        float4 b = *(float4*)&s_shift[f];
        v.x = fmaxf(fmaf(v.x, g.x, b.x), 0.f) * d;
        v.y = fmaxf(fmaf(v.y, g.y, b.y), 0.f) * d;
        v.z = fmaxf(fmaf(v.z, g.z, b.z), 0.f) * d;
        v.w = fmaxf(fmaf(v.w, g.w, b.w), 0.f) * d;
        __half2* dst = (__half2*)&g_hn[(size_t)i * 4];
        dst[0] = __floats2half2_rn(v.x, v.y);
        dst[1] = __floats2half2_rn(v.z, v.w);
    }
}

// ---------------- launch ----------------
extern "C" void kernel_launch(void* const* d_in, const int* in_sizes, int n_in,
                              void* d_out, int out_size) {
    const float* x      = (const float*)d_in[0];
    const int*   ei     = (const int*)d_in[1];
    const float* lin1_w = (const float*)d_in[2];
    const float* lin1_b = (const float*)d_in[3];
    const float* w1     = (const float*)d_in[4];
    const float* w2     = (const float*)d_in[5];
    const float* gamma  = (const float*)d_in[6];
    const float* betab  = (const float*)d_in[7];
    const float* lin2_w = (const float*)d_in[8];
    const float* lin2_b = (const float*)d_in[9];
    float* out = (float*)d_out;

    int N = in_sizes[0] / 128;
    int E = in_sizes[1] / 2;
    const int* row = ei;
    const int* col = ei + E;

    int Mt = (N + 127) / 128;
    int Mt2 = (N + 255) / 256;
    int total4 = N * (DH / 4);
    float invcnt = 1.0f / ((float)N * (float)DH);

    static int smem_set = 0;
    if (!smem_set) {
        cudaFuncSetAttribute(k_mma, cudaFuncAttributeMaxDynamicSharedMemorySize, SMTOT);
        cudaFuncSetAttribute(k_lin1, cudaFuncAttributeMaxDynamicSharedMemorySize, SMTOT);
        cudaFuncSetAttribute(k_lin2, cudaFuncAttributeMaxDynamicSharedMemorySize, L2SMTOT);
        smem_set = 1;
    }

    k_init<<<(N + 255) / 256, 256>>>(N);
    k_count<<<(E + 255) / 256, 256>>>(col, E);
    k_scan<<<1, 1024>>>(N, E);
    k_scatter<<<(E + 255) / 256, 256>>>(row, col, E);
    k_prep_b<<<(NL * 512 * 256 + 255) / 256, 256>>>(w1, w2);
    k_prep_x<<<(N * 128 + 255) / 256, 256>>>(x, N * 128);
    k_prep_w<<<(2 * 128 * 256 + 255) / 256, 256>>>(lin1_w, lin2_w);

    // x0 = relu(x @ lin1_w + b) -> dis*x0 in g_hn, x0 in g_a upper-k
    k_lin1<<<Mt, 256, SMTOT>>>(lin1_b, N);

    for (int l = 0; l < NL; l++) {
        k_gather<<<(N * 32 + 255) / 256, 256>>>(N);
        k_mma<<<Mt, 256, SMTOT>>>(l, N);
        // prescale by dis for layers feeding the next gather; last layer unscaled (feeds lin2)
        k_norm<<<1184, 256>>>(gamma + l * DH, betab + l * DH, total4, Mt, invcnt,
                              (l < NL - 1) ? 1 : 0);
    }

    // out = relu(norm7(h) @ lin2_w + b)
    k_lin2<<<Mt2, 256, L2SMTOT>>>(lin2_b, out, N);
}

// round 15
// speedup vs baseline: 1.0477x; 1.0088x over previous
#include <cuda_runtime.h>
#include <cuda_fp16.h>
#include <math.h>
#include <stdint.h>

#define NN 50000
#define EE 800000
#define DH 256
#define NL 8
#define NTILES ((NN + 127) / 128)        // 391
#define NPAD (NTILES * 128)              // 50048
#define NT2 ((NN + 255) / 256)           // 196
#define NPAD2 (NT2 * 256)                // 50176

// ---------------- scratch ----------------
__device__ float g_ha[NN * DH];                                  // fp32 h_out (per-layer)
__device__ __align__(16) __half g_hn[(size_t)NPAD2 * DH];        // fp16 dis*relu(norm(h)) / dis*x0
__device__ __align__(16) __half g_a[(size_t)NPAD * 512];         // fp16 A [node][k] k<256 agg, k>=256 x0
__device__ __align__(16) __half g_bh[(size_t)NL * 512 * 256];    // B' hi
__device__ __align__(16) __half g_bl[(size_t)NL * 512 * 256];    // B' lo
__device__ __align__(16) __half g_x16[(size_t)NPAD * 128];       // fp16 x
__device__ __align__(16) __half g_w1h[128 * 256], g_w1l[128 * 256];
__device__ __align__(16) __half g_w2h[256 * 128], g_w2l[256 * 128];
__device__ float g_dis[NN];
__device__ int   g_counts[NN];
__device__ int   g_cursor[NN];
__device__ int   g_rowptr[NN + 1];
__device__ int   g_csr[EE];
__device__ float g_part[NTILES + 8];
__device__ float g_part2[NTILES + 8];

// ---------------- helpers ----------------
__device__ __forceinline__ uint32_t s2u(const void* p) {
    uint32_t a;
    asm("{ .reg .u64 t; cvta.to.shared.u64 t, %1; cvt.u32.u64 %0, t; }" : "=r"(a) : "l"(p));
    return a;
}
__device__ __forceinline__ void cp16(uint32_t dst, const void* src) {
    asm volatile("cp.async.cg.shared.global [%0], [%1], 16;" :: "r"(dst), "l"(src) : "memory");
}
#define CP_COMMIT() asm volatile("cp.async.commit_group;" ::: "memory")
#define CP_WAIT(n)  asm volatile("cp.async.wait_group %0;" :: "n"(n) : "memory")

#define LDSM4(r0,r1,r2,r3,a) \
    asm volatile("ldmatrix.sync.aligned.m8n8.x4.shared.b16 {%0,%1,%2,%3}, [%4];" \
                 : "=r"(r0),"=r"(r1),"=r"(r2),"=r"(r3) : "r"(a))
#define LDSM4T(r0,r1,r2,r3,a) \
    asm volatile("ldmatrix.sync.aligned.m8n8.x4.trans.shared.b16 {%0,%1,%2,%3}, [%4];" \
                 : "=r"(r0),"=r"(r1),"=r"(r2),"=r"(r3) : "r"(a))
#define MMA_F16(c,a,b0,b1) \
    asm volatile("mma.sync.aligned.m16n8k16.row.col.f32.f16.f16.f32 " \
                 "{%0,%1,%2,%3}, {%4,%5,%6,%7}, {%8,%9}, {%0,%1,%2,%3};" \
                 : "+f"((c)[0]),"+f"((c)[1]),"+f"((c)[2]),"+f"((c)[3]) \
                 : "r"((a)[0]),"r"((a)[1]),"r"((a)[2]),"r"((a)[3]),"r"(b0),"r"(b1))

__device__ __forceinline__ void split_h(float v, __half& h, __half& l) {
    h = __float2half_rn(v);
    l = __float2half_rn(v - __half2float(h));
}

// ---------------- graph preprocessing ----------------
__global__ void k_count(const int* __restrict__ col, int E) {
    int e = blockIdx.x * blockDim.x + threadIdx.x;
    if (e < E) atomicAdd(&g_counts[col[e]], 1);
}
__global__ void k_scan(int n, int E) {
    __shared__ int sh[1024];
    int tid = threadIdx.x;
    int C = (n + 1023) >> 10;
    int base = tid * C;
    int s = 0;
    for (int i = 0; i < C; i++) { int idx = base + i; if (idx < n) s += g_counts[idx]; }
    sh[tid] = s; __syncthreads();
    for (int off = 1; off < 1024; off <<= 1) {
        int v = (tid >= off) ? sh[tid - off] : 0;
        __syncthreads();
        sh[tid] += v;
        __syncthreads();
    }
    int run = (tid > 0) ? sh[tid - 1] : 0;
    for (int i = 0; i < C; i++) {
        int idx = base + i;
        if (idx < n) {
            g_rowptr[idx] = run;
            int c = g_counts[idx];
            run += c;
            g_dis[idx] = rsqrtf((float)(c + 1));
        }
    }
    if (tid == 0) g_rowptr[n] = E;
}
__global__ void k_scatter(const int* __restrict__ row, const int* __restrict__ col, int E) {
    int e = blockIdx.x * blockDim.x + threadIdx.x;
    if (e < E) {
        int c = col[e];
        int p = g_rowptr[c] + atomicAdd(&g_cursor[c], 1);
        g_csr[p] = row[e];
    }
}

// ---------------- unified prep: zero counts/cursor, fp16 x, W1/W2 split, B' split ----------------
#define PB_ELEMS (NL * 512 * 256)
__global__ void k_prep_all(const float* __restrict__ w1, const float* __restrict__ w2,
                           const float* __restrict__ x, int xtotal,
                           const float* __restrict__ l1w, const float* __restrict__ l2w,
                           int n) {
    int i = blockIdx.x * blockDim.x + threadIdx.x;
    if (i < PB_ELEMS) {
        int nn = i & 255;
        int k = (i >> 8) & 511;
        int l = i >> 17;
        float beta = logf(1.0f / (float)(l + 1) + 1.0f);
        float v = (k < 256) ? w1[(l << 16) + (k << 8) + nn]
                            : w2[(l << 16) + ((k - 256) << 8) + nn];
        float val = 0.5f * beta * v;
        if (k == nn || k == nn + 256) val += 0.5f * (1.0f - beta);
        split_h(val, g_bh[i], g_bl[i]);
        return;
    }
    int j = i - PB_ELEMS;
    if (j < xtotal) { g_x16[j] = __float2half_rn(x[j]); return; }
    j -= xtotal;
    if (j < 128 * 256) { split_h(l1w[j], g_w1h[j], g_w1l[j]); return; }
    j -= 128 * 256;
    if (j < 256 * 128) { split_h(l2w[j], g_w2h[j], g_w2l[j]); return; }
    j -= 256 * 128;
    if (j < n) { g_counts[j] = 0; g_cursor[j] = 0; }
}

// ---------------- CSR gather (dis pre-folded into g_hn) -> fp16 A rows (k 0..255) ----------------
__global__ __launch_bounds__(256) void k_gather(int n) {
    int w = (blockIdx.x * blockDim.x + threadIdx.x) >> 5;
    int lane = threadIdx.x & 31;
    if (w >= n) return;
    const uint4* __restrict__ hn = (const uint4*)g_hn;
    float dc = g_dis[w];
    float a[8];
    {
        uint4 v = hn[w * 32 + lane];
        const __half2* ph = (const __half2*)&v;
#pragma unroll
        for (int j = 0; j < 4; j++) {
            float2 f = __half22float2(ph[j]);
            a[2 * j] = f.x; a[2 * j + 1] = f.y;
        }
    }
    int beg = g_rowptr[w], end = g_rowptr[w + 1];
    int i = beg;
    for (; i + 3 < end; i += 4) {
        int s0 = g_csr[i], s1 = g_csr[i + 1], s2 = g_csr[i + 2], s3 = g_csr[i + 3];
        uint4 p = hn[s0 * 32 + lane], q = hn[s1 * 32 + lane];
        uint4 r = hn[s2 * 32 + lane], t = hn[s3 * 32 + lane];
        const __half2* pp = (const __half2*)&p;
        const __half2* qq = (const __half2*)&q;
        const __half2* rr = (const __half2*)&r;
        const __half2* tt = (const __half2*)&t;
#pragma unroll
        for (int j = 0; j < 4; j++) {
            float2 fp = __half22float2(pp[j]);
            float2 fq = __half22float2(qq[j]);
            float2 fr = __half22float2(rr[j]);
            float2 ft = __half22float2(tt[j]);
            a[2 * j]     += (fp.x + fq.x) + (fr.x + ft.x);
            a[2 * j + 1] += (fp.y + fq.y) + (fr.y + ft.y);
        }
    }
    for (; i < end; i++) {
        int s0 = g_csr[i];
        uint4 p = hn[s0 * 32 + lane];
        const __half2* pp = (const __half2*)&p;
#pragma unroll
        for (int j = 0; j < 4; j++) {
            float2 fp = __half22float2(pp[j]);
            a[2 * j]     += fp.x;
            a[2 * j + 1] += fp.y;
        }
    }
    size_t ro = (size_t)w * 512 + lane * 8;
    __half hh[8];
#pragma unroll
    for (int j = 0; j < 8; j++) hh[j] = __float2half_rn(a[j] * dc);
    *(uint4*)&g_a[ro] = *(uint4*)hh;
}

// ---------------- layer GEMM: fp16 2-pass, 128m x 256n, K=512 (8x64) ----------------
#define STAGE 81920u
#define SMTOT 163840
__global__ __launch_bounds__(256, 1) void k_mma(int layer, int nvalid) {
    extern __shared__ char smem[];
    uint32_t sb = s2u(smem);
    const int tid = threadIdx.x, lane = tid & 31, wid = tid >> 5;
    const int T = blockIdx.x;

    const __half* __restrict__ Ag = g_a + (size_t)T * 128 * 512;
    const __half* __restrict__ Bgh = g_bh + (size_t)layer * 512 * 256;
    const __half* __restrict__ Bgl = g_bl + (size_t)layer * 512 * 256;

    auto load_chunk = [&](int c, int st) {
        uint32_t s0 = sb + st * STAGE;
#pragma unroll
        for (int i = 0; i < 4; i++) {
            int e = tid + i * 256;
            int m = e >> 3, kc = e & 7;
            uint32_t da = (uint32_t)(m * 128 + ((kc ^ (m & 7)) << 4));
            cp16(s0 + da, Ag + (size_t)m * 512 + c * 64 + kc * 8);
        }
#pragma unroll
        for (int i = 0; i < 8; i++) {
            int e = tid + i * 256;
            int k = e >> 5, ncol = e & 31;
            int nhalf = ncol >> 4, nc = ncol & 15;
            uint32_t db = (uint32_t)(nhalf * 16384 + k * 256 + ((nc ^ (k & 7)) << 4));
            size_t src = (size_t)(c * 64 + k) * 256 + nhalf * 128 + nc * 8;
            cp16(s0 + 16384 + db, Bgh + src);
            cp16(s0 + 49152 + db, Bgl + src);
        }
        CP_COMMIT();
    };

    float acc[4][8][4];
#pragma unroll
    for (int i = 0; i < 4; i++)
#pragma unroll
        for (int j = 0; j < 8; j++)
#pragma unroll
            for (int q = 0; q < 4; q++) acc[i][j][q] = 0.f;

    const int wm = (wid & 1) * 64;
    const int wng = (wid >> 1) * 64;
    const uint32_t nhb = (uint32_t)((wng >> 7) * 16384);
    const int ncb = (wng & 127) >> 3;

    auto compute = [&](uint32_t s0) {
        uint32_t sa = s0, sbh = s0 + 16384, sbl = s0 + 49152;
#pragma unroll
        for (int kq = 0; kq < 4; kq++) {
            uint32_t ar[4][4], bh[4][4], bl[4][4];
#pragma unroll
            for (int mi = 0; mi < 4; mi++) {
                int m = wm + mi * 16 + (lane & 15);
                int kcc = kq * 2 + (lane >> 4);
                uint32_t ad = (uint32_t)(m * 128 + ((kcc ^ (m & 7)) << 4));
                LDSM4(ar[mi][0], ar[mi][1], ar[mi][2], ar[mi][3], sa + ad);
            }
#pragma unroll
            for (int nj = 0; nj < 4; nj++) {
                int kr = kq * 16 + (lane & 15);
                int nc = ncb + nj * 2 + (lane >> 4);
                uint32_t bd = nhb + (uint32_t)(kr * 256 + ((nc ^ (kr & 7)) << 4));
                LDSM4T(bh[nj][0], bh[nj][1], bh[nj][2], bh[nj][3], sbh + bd);
                LDSM4T(bl[nj][0], bl[nj][1], bl[nj][2], bl[nj][3], sbl + bd);
            }
#pragma unroll
            for (int mi = 0; mi < 4; mi++)
#pragma unroll
                for (int nt = 0; nt < 8; nt++) {
                    int nj = nt >> 1, pq = (nt & 1) * 2;
                    MMA_F16(acc[mi][nt], ar[mi], bh[nj][pq], bh[nj][pq + 1]);
                    MMA_F16(acc[mi][nt], ar[mi], bl[nj][pq], bl[nj][pq + 1]);
                }
        }
    };

    load_chunk(0, 0);
    for (int ch = 0; ch < 8; ch++) {
        if (ch < 7) { load_chunk(ch + 1, (ch + 1) & 1); CP_WAIT(1); }
        else        { CP_WAIT(0); }
        __syncthreads();
        compute(sb + (ch & 1) * STAGE);
        __syncthreads();
    }

    // ---- epilogue: write g_ha, LN partials via shuffle reduce ----
    float s = 0.f, ss = 0.f;
    int rbase = T * 128 + wm + (lane >> 2);
    int cbase = wng + (lane & 3) * 2;
#pragma unroll
    for (int mi = 0; mi < 4; mi++) {
        int r0 = rbase + mi * 16;
        int r1 = r0 + 8;
        bool v0 = r0 < nvalid, v1 = r1 < nvalid;
#pragma unroll
        for (int nt = 0; nt < 8; nt++) {
            int col = cbase + nt * 8;
            if (v0) {
                float2 p = make_float2(acc[mi][nt][0], acc[mi][nt][1]);
                *(float2*)&g_ha[(size_t)r0 * DH + col] = p;
                s += p.x + p.y; ss += p.x * p.x + p.y * p.y;
            }
            if (v1) {
                float2 p = make_float2(acc[mi][nt][2], acc[mi][nt][3]);
                *(float2*)&g_ha[(size_t)r1 * DH + col] = p;
                s += p.x + p.y; ss += p.x * p.x + p.y * p.y;
            }
        }
    }
#pragma unroll
    for (int o = 16; o > 0; o >>= 1) {
        s += __shfl_xor_sync(0xffffffffu, s, o);
        ss += __shfl_xor_sync(0xffffffffu, ss, o);
    }
    __syncthreads();                 // all warps done reading smem stages
    float* red = (float*)smem;
    if (lane == 0) { red[wid] = s; red[8 + wid] = ss; }
    __syncthreads();
    if (tid == 0) {
        float a = 0.f, b = 0.f;
#pragma unroll
        for (int i = 0; i < 8; i++) { a += red[i]; b += red[8 + i]; }
        g_part[T] = a; g_part2[T] = b;
    }
}

// ---------------- lin1: fp16 2-pass, 128m x 256n, K=128 (2x64) ----------------
__global__ __launch_bounds__(256, 1) void k_lin1(const float* __restrict__ bias, int nvalid) {
    extern __shared__ char smem[];
    uint32_t sb = s2u(smem);
    const int tid = threadIdx.x, lane = tid & 31, wid = tid >> 5;
    const int T = blockIdx.x;

    auto load_chunk = [&](int c, int st) {
        uint32_t s0 = sb + st * STAGE;
#pragma unroll
        for (int i = 0; i < 4; i++) {
            int e = tid + i * 256;
            int m = e >> 3, kc = e & 7;
            uint32_t da = (uint32_t)(m * 128 + ((kc ^ (m & 7)) << 4));
            cp16(s0 + da, g_x16 + (size_t)(T * 128 + m) * 128 + c * 64 + kc * 8);
        }
#pragma unroll
        for (int i = 0; i < 8; i++) {
            int e = tid + i * 256;
            int k = e >> 5, ncol = e & 31;
            int nhalf = ncol >> 4, nc = ncol & 15;
            uint32_t db = (uint32_t)(nhalf * 16384 + k * 256 + ((nc ^ (k & 7)) << 4));
            size_t src = (size_t)(c * 64 + k) * 256 + nhalf * 128 + nc * 8;
            cp16(s0 + 16384 + db, g_w1h + src);
            cp16(s0 + 49152 + db, g_w1l + src);
        }
        CP_COMMIT();
    };

    float acc[4][8][4];
#pragma unroll
    for (int i = 0; i < 4; i++)
#pragma unroll
        for (int j = 0; j < 8; j++)
#pragma unroll
            for (int q = 0; q < 4; q++) acc[i][j][q] = 0.f;

    const int wm = (wid & 1) * 64;
    const int wng = (wid >> 1) * 64;
    const uint32_t nhb = (uint32_t)((wng >> 7) * 16384);
    const int ncb = (wng & 127) >> 3;

    auto compute = [&](uint32_t s0) {
        uint32_t sa = s0, sbh = s0 + 16384, sbl = s0 + 49152;
#pragma unroll
        for (int kq = 0; kq < 4; kq++) {
            uint32_t ar[4][4], bh[4][4], bl[4][4];
#pragma unroll
            for (int mi = 0; mi < 4; mi++) {
                int m = wm + mi * 16 + (lane & 15);
                int kcc = kq * 2 + (lane >> 4);
                uint32_t ad = (uint32_t)(m * 128 + ((kcc ^ (m & 7)) << 4));
                LDSM4(ar[mi][0], ar[mi][1], ar[mi][2], ar[mi][3], sa + ad);
            }
#pragma unroll
            for (int nj = 0; nj < 4; nj++) {
                int kr = kq * 16 + (lane & 15);
                int nc = ncb + nj * 2 + (lane >> 4);
                uint32_t bd = nhb + (uint32_t)(kr * 256 + ((nc ^ (kr & 7)) << 4));
                LDSM4T(bh[nj][0], bh[nj][1], bh[nj][2], bh[nj][3], sbh + bd);
                LDSM4T(bl[nj][0], bl[nj][1], bl[nj][2], bl[nj][3], sbl + bd);
            }
#pragma unroll
            for (int mi = 0; mi < 4; mi++)
#pragma unroll
                for (int nt = 0; nt < 8; nt++) {
                    int nj = nt >> 1, pq = (nt & 1) * 2;
                    MMA_F16(acc[mi][nt], ar[mi], bh[nj][pq], bh[nj][pq + 1]);
                    MMA_F16(acc[mi][nt], ar[mi], bl[nj][pq], bl[nj][pq + 1]);
                }
        }
    };

    load_chunk(0, 0);
    load_chunk(1, 1);
    CP_WAIT(1);
    __syncthreads();
    compute(sb);
    __syncthreads();
    CP_WAIT(0);
    __syncthreads();
    compute(sb + STAGE);

    int rbase = T * 128 + wm + (lane >> 2);
    int cbase = wng + (lane & 3) * 2;
#pragma unroll
    for (int mi = 0; mi < 4; mi++) {
        int r0 = rbase + mi * 16;
        int r1 = r0 + 8;
        float d0 = (r0 < nvalid) ? g_dis[r0] : 0.f;
        float d1 = (r1 < nvalid) ? g_dis[r1] : 0.f;
#pragma unroll
        for (int nt = 0; nt < 8; nt++) {
            int col = cbase + nt * 8;
            float2 bb = *(const float2*)&bias[col];
            float v0 = fmaxf(acc[mi][nt][0] + bb.x, 0.f);
            float v1 = fmaxf(acc[mi][nt][1] + bb.y, 0.f);
            *(__half2*)&g_a[(size_t)r0 * 512 + 256 + col] = __floats2half2_rn(v0, v1);
            if (r0 < nvalid)
                *(__half2*)&g_hn[(size_t)r0 * DH + col] = __floats2half2_rn(v0 * d0, v1 * d0);
            float v2 = fmaxf(acc[mi][nt][2] + bb.x, 0.f);
            float v3 = fmaxf(acc[mi][nt][3] + bb.y, 0.f);
            *(__half2*)&g_a[(size_t)r1 * 512 + 256 + col] = __floats2half2_rn(v2, v3);
            if (r1 < nvalid)
                *(__half2*)&g_hn[(size_t)r1 * DH + col] = __floats2half2_rn(v2 * d1, v3 * d1);
        }
    }
}

// ---------------- lin2: fp16 2-pass, 256m x 128n, K=256 (4x64) ----------------
#define L2STAGE 65536u
#define L2SMTOT 131072
__global__ __launch_bounds__(256, 1) void k_lin2(const float* __restrict__ bias,
                                                 float* __restrict__ out, int nvalid) {
    extern __shared__ char smem[];
    uint32_t sb = s2u(smem);
    const int tid = threadIdx.x, lane = tid & 31, wid = tid >> 5;
    const int T = blockIdx.x;

    auto load_chunk = [&](int c, int st) {
        uint32_t s0 = sb + st * L2STAGE;
#pragma unroll
        for (int i = 0; i < 8; i++) {
            int e = tid + i * 256;
            int m = e >> 3, kc = e & 7;
            uint32_t da = (uint32_t)(m * 128 + ((kc ^ (m & 7)) << 4));
            cp16(s0 + da, g_hn + (size_t)(T * 256 + m) * DH + c * 64 + kc * 8);
        }
#pragma unroll
        for (int i = 0; i < 4; i++) {
            int e = tid + i * 256;
            int k = e >> 4, nc = e & 15;
            uint32_t db = (uint32_t)(k * 256 + ((nc ^ (k & 7)) << 4));
            size_t src = (size_t)(c * 64 + k) * 128 + nc * 8;
            cp16(s0 + 32768 + db, g_w2h + src);
            cp16(s0 + 49152 + db, g_w2l + src);
        }
        CP_COMMIT();
    };

    float acc[4][8][4];
#pragma unroll
    for (int i = 0; i < 4; i++)
#pragma unroll
        for (int j = 0; j < 8; j++)
#pragma unroll
            for (int q = 0; q < 4; q++) acc[i][j][q] = 0.f;

    const int wm = (wid & 3) * 64;
    const int wn = (wid >> 2) * 64;
    const int ncb = wn >> 3;

    auto compute = [&](uint32_t s0) {
        uint32_t sa = s0, sbh = s0 + 32768, sbl = s0 + 49152;
#pragma unroll
        for (int kq = 0; kq < 4; kq++) {
            uint32_t ar[4][4], bh[4][4], bl[4][4];
#pragma unroll
            for (int mi = 0; mi < 4; mi++) {
                int m = wm + mi * 16 + (lane & 15);
                int kcc = kq * 2 + (lane >> 4);
                uint32_t ad = (uint32_t)(m * 128 + ((kcc ^ (m & 7)) << 4));
                LDSM4(ar[mi][0], ar[mi][1], ar[mi][2], ar[mi][3], sa + ad);
            }
#pragma unroll
            for (int nj = 0; nj < 4; nj++) {
                int kr = kq * 16 + (lane & 15);
                int nc = ncb + nj * 2 + (lane >> 4);
                uint32_t bd = (uint32_t)(kr * 256 + ((nc ^ (kr & 7)) << 4));
                LDSM4T(bh[nj][0], bh[nj][1], bh[nj][2], bh[nj][3], sbh + bd);
                LDSM4T(bl[nj][0], bl[nj][1], bl[nj][2], bl[nj][3], sbl + bd);
            }
#pragma unroll
            for (int mi = 0; mi < 4; mi++)
#pragma unroll
                for (int nt = 0; nt < 8; nt++) {
                    int nj = nt >> 1, pq = (nt & 1) * 2;
                    MMA_F16(acc[mi][nt], ar[mi], bh[nj][pq], bh[nj][pq + 1]);
                    MMA_F16(acc[mi][nt], ar[mi], bl[nj][pq], bl[nj][pq + 1]);
                }
        }
    };

    load_chunk(0, 0);
    for (int ch = 0; ch < 4; ch++) {
        if (ch < 3) { load_chunk(ch + 1, (ch + 1) & 1); CP_WAIT(1); }
        else        { CP_WAIT(0); }
        __syncthreads();
        compute(sb + (ch & 1) * L2STAGE);
        __syncthreads();
    }

    int rbase = T * 256 + wm + (lane >> 2);
    int cbase = wn + (lane & 3) * 2;
#pragma unroll
    for (int mi = 0; mi < 4; mi++) {
        int r0 = rbase + mi * 16;
        int r1 = r0 + 8;
        bool v0 = r0 < nvalid, v1 = r1 < nvalid;
#pragma unroll
        for (int nt = 0; nt < 8; nt++) {
            int col = cbase + nt * 8;
            float2 bb = *(const float2*)&bias[col];
            if (v0) {
                float2 p = make_float2(fmaxf(acc[mi][nt][0] + bb.x, 0.f),
                                       fmaxf(acc[mi][nt][1] + bb.y, 0.f));
                *(float2*)&out[(size_t)r0 * 128 + col] = p;
            }
            if (v1) {
                float2 p = make_float2(fmaxf(acc[mi][nt][2] + bb.x, 0.f),
                                       fmaxf(acc[mi][nt][3] + bb.y, 0.f));
                *(float2*)&out[(size_t)r1 * 128 + col] = p;
            }
        }
    }
}

// ---------------- layernorm: finalize + normalize+relu (+dis prescale) ----------------
__global__ __launch_bounds__(256) void k_norm(const float* __restrict__ gamma,
                                              const float* __restrict__ beta,
                                              int total4, int nparts, float invcnt, int scale_dis) {
    __shared__ float sred[512];
    __shared__ float s_scale[256], s_shift[256];
    const int tid = threadIdx.x;

    float s = 0.f, ss = 0.f;
    for (int i = tid; i < nparts; i += 256) { s += g_part[i]; ss += g_part2[i]; }
    sred[tid] = s; sred[256 + tid] = ss;
    __syncthreads();
    for (int o = 128; o > 0; o >>= 1) {
        if (tid < o) { sred[tid] += sred[tid + o]; sred[256 + tid] += sred[256 + tid + o]; }
        __syncthreads();
    }
    float mu = sred[0] * invcnt;
    float var = fmaxf(sred[256] * invcnt - mu * mu, 0.f);
    float inv = 1.0f / (sqrtf(var) + 1e-5f);
    float gch = gamma[tid] * inv;
    s_scale[tid] = gch;
    s_shift[tid] = beta[tid] - mu * gch;
    __syncthreads();

    int stride = gridDim.x * 256;
    for (int i = blockIdx.x * 256 + tid; i < total4; i += stride) {
        float4 v = ((const float4*)g_ha)[i];
        int f = (i * 4) & 255;
        int node = i >> 6;
        float d = scale_dis ? g_dis[node] : 1.0f;
        float4 g = *(float4*)&s_scale[f];
        float4 b = *(float4*)&s_shift[f];
        v.x = fmaxf(fmaf(v.x, g.x, b.x), 0.f) * d;
        v.y = fmaxf(fmaf(v.y, g.y, b.y), 0.f) * d;
        v.z = fmaxf(fmaf(v.z, g.z, b.z), 0.f) * d;
        v.w = fmaxf(fmaf(v.w, g.w, b.w), 0.f) * d;
        __half2* dst = (__half2*)&g_hn[(size_t)i * 4];
        dst[0] = __floats2half2_rn(v.x, v.y);
        dst[1] = __floats2half2_rn(v.z, v.w);
    }
}

// ---------------- launch ----------------
extern "C" void kernel_launch(void* const* d_in, const int* in_sizes, int n_in,
                              void* d_out, int out_size) {
    const float* x      = (const float*)d_in[0];
    const int*   ei     = (const int*)d_in[1];
    const float* lin1_w = (const float*)d_in[2];
    const float* lin1_b = (const float*)d_in[3];
    const float* w1     = (const float*)d_in[4];
    const float* w2     = (const float*)d_in[5];
    const float* gamma  = (const float*)d_in[6];
    const float* betab  = (const float*)d_in[7];
    const float* lin2_w = (const float*)d_in[8];
    const float* lin2_b = (const float*)d_in[9];
    float* out = (float*)d_out;

    int N = in_sizes[0] / 128;
    int E = in_sizes[1] / 2;
    const int* row = ei;
    const int* col = ei + E;

    int Mt = (N + 127) / 128;
    int Mt2 = (N + 255) / 256;
    int total4 = N * (DH / 4);
    float invcnt = 1.0f / ((float)N * (float)DH);
    int xtotal = N * 128;
    int prep_total = PB_ELEMS + xtotal + 128 * 256 + 256 * 128 + N;

    static int smem_set = 0;
    if (!smem_set) {
        cudaFuncSetAttribute(k_mma, cudaFuncAttributeMaxDynamicSharedMemorySize, SMTOT);
        cudaFuncSetAttribute(k_lin1, cudaFuncAttributeMaxDynamicSharedMemorySize, SMTOT);
        cudaFuncSetAttribute(k_lin2, cudaFuncAttributeMaxDynamicSharedMemorySize, L2SMTOT);
        smem_set = 1;
    }

    // unified prep (also zeroes counts/cursor)
    k_prep_all<<<(prep_total + 255) / 256, 256>>>(w1, w2, x, xtotal, lin1_w, lin2_w, N);
    k_count<<<(E + 255) / 256, 256>>>(col, E);
    k_scan<<<1, 1024>>>(N, E);
    k_scatter<<<(E + 255) / 256, 256>>>(row, col, E);

    // x0 = relu(x @ lin1_w + b) -> dis*x0 in g_hn, x0 in g_a upper-k
    k_lin1<<<Mt, 256, SMTOT>>>(lin1_b, N);

    for (int l = 0; l < NL; l++) {
        k_gather<<<(N * 32 + 255) / 256, 256>>>(N);
        k_mma<<<Mt, 256, SMTOT>>>(l, N);
        k_norm<<<1184, 256>>>(gamma + l * DH, betab + l * DH, total4, Mt, invcnt,
                              (l < NL - 1) ? 1 : 0);
    }

    // out = relu(norm7(h) @ lin2_w + b)
    k_lin2<<<Mt2, 256, L2SMTOT>>>(lin2_b, out, N);
}

// round 16
// speedup vs baseline: 1.0621x; 1.0138x over previous
#include <cuda_runtime.h>
#include <cuda_fp16.h>
#include <math.h>
#include <stdint.h>

#define NN 50000
#define EE 800000
#define DH 256
#define NL 8
#define NTILES ((NN + 127) / 128)        // 391
#define NPAD (NTILES * 128)              // 50048
#define NT2 ((NN + 255) / 256)           // 196
#define NPAD2 (NT2 * 256)                // 50176

// ---------------- scratch ----------------
__device__ float g_ha[NN * DH];                                  // fp32 h_out (per-layer)
__device__ __align__(16) __half g_hn[(size_t)NPAD2 * DH];        // fp16 dis*relu(norm(h)) / dis*x0
__device__ __align__(16) __half g_a[(size_t)NPAD * 512];         // fp16 A [node][k] k<256 agg, k>=256 x0
__device__ __align__(16) __half g_bh[(size_t)NL * 512 * 256];    // B' hi
__device__ __align__(16) __half g_bl[(size_t)NL * 512 * 256];    // B' lo
__device__ __align__(16) __half g_x16[(size_t)NPAD * 128];       // fp16 x
__device__ __align__(16) __half g_w1h[128 * 256], g_w1l[128 * 256];
__device__ __align__(16) __half g_w2h[256 * 128], g_w2l[256 * 128];
__device__ float g_dis[NN];
__device__ int   g_counts[NN];
__device__ int   g_cursor[NN];
__device__ int   g_rowptr[NN + 1];
__device__ int   g_csr[EE];
__device__ float g_part[NTILES + 8];
__device__ float g_part2[NTILES + 8];

// ---------------- helpers ----------------
__device__ __forceinline__ uint32_t s2u(const void* p) {
    uint32_t a;
    asm("{ .reg .u64 t; cvta.to.shared.u64 t, %1; cvt.u32.u64 %0, t; }" : "=r"(a) : "l"(p));
    return a;
}
__device__ __forceinline__ void cp16(uint32_t dst, const void* src) {
    asm volatile("cp.async.cg.shared.global [%0], [%1], 16;" :: "r"(dst), "l"(src) : "memory");
}
#define CP_COMMIT() asm volatile("cp.async.commit_group;" ::: "memory")
#define CP_WAIT(n)  asm volatile("cp.async.wait_group %0;" :: "n"(n) : "memory")

#define LDSM4(r0,r1,r2,r3,a) \
    asm volatile("ldmatrix.sync.aligned.m8n8.x4.shared.b16 {%0,%1,%2,%3}, [%4];" \
                 : "=r"(r0),"=r"(r1),"=r"(r2),"=r"(r3) : "r"(a))
#define LDSM4T(r0,r1,r2,r3,a) \
    asm volatile("ldmatrix.sync.aligned.m8n8.x4.trans.shared.b16 {%0,%1,%2,%3}, [%4];" \
                 : "=r"(r0),"=r"(r1),"=r"(r2),"=r"(r3) : "r"(a))
#define MMA_F16(c,a,b0,b1) \
    asm volatile("mma.sync.aligned.m16n8k16.row.col.f32.f16.f16.f32 " \
                 "{%0,%1,%2,%3}, {%4,%5,%6,%7}, {%8,%9}, {%0,%1,%2,%3};" \
                 : "+f"((c)[0]),"+f"((c)[1]),"+f"((c)[2]),"+f"((c)[3]) \
                 : "r"((a)[0]),"r"((a)[1]),"r"((a)[2]),"r"((a)[3]),"r"(b0),"r"(b1))

__device__ __forceinline__ void split_h(float v, __half& h, __half& l) {
    h = __float2half_rn(v);
    l = __float2half_rn(v - __half2float(h));
}

// ---------------- graph preprocessing ----------------
__global__ void k_count(const int* __restrict__ col, int E) {
    int e = blockIdx.x * blockDim.x + threadIdx.x;
    if (e < E) atomicAdd(&g_counts[col[e]], 1);
}
__global__ void k_scan(int n, int E) {
    __shared__ int sh[1024];
    int tid = threadIdx.x;
    int C = (n + 1023) >> 10;
    int base = tid * C;
    int s = 0;
    for (int i = 0; i < C; i++) { int idx = base + i; if (idx < n) s += g_counts[idx]; }
    sh[tid] = s; __syncthreads();
    for (int off = 1; off < 1024; off <<= 1) {
        int v = (tid >= off) ? sh[tid - off] : 0;
        __syncthreads();
        sh[tid] += v;
        __syncthreads();
    }
    int run = (tid > 0) ? sh[tid - 1] : 0;
    for (int i = 0; i < C; i++) {
        int idx = base + i;
        if (idx < n) {
            g_rowptr[idx] = run;
            int c = g_counts[idx];
            run += c;
            g_dis[idx] = rsqrtf((float)(c + 1));
        }
    }
    if (tid == 0) g_rowptr[n] = E;
}
__global__ void k_scatter(const int* __restrict__ row, const int* __restrict__ col, int E) {
    int e = blockIdx.x * blockDim.x + threadIdx.x;
    if (e < E) {
        int c = col[e];
        int p = g_rowptr[c] + atomicAdd(&g_cursor[c], 1);
        g_csr[p] = row[e];
    }
}

// ---------------- unified prep ----------------
#define PB_ELEMS (NL * 512 * 256)
__global__ void k_prep_all(const float* __restrict__ w1, const float* __restrict__ w2,
                           const float* __restrict__ x, int xtotal,
                           const float* __restrict__ l1w, const float* __restrict__ l2w,
                           int n) {
    int i = blockIdx.x * blockDim.x + threadIdx.x;
    if (i < PB_ELEMS) {
        int nn = i & 255;
        int k = (i >> 8) & 511;
        int l = i >> 17;
        float beta = logf(1.0f / (float)(l + 1) + 1.0f);
        float v = (k < 256) ? w1[(l << 16) + (k << 8) + nn]
                            : w2[(l << 16) + ((k - 256) << 8) + nn];
        float val = 0.5f * beta * v;
        if (k == nn || k == nn + 256) val += 0.5f * (1.0f - beta);
        split_h(val, g_bh[i], g_bl[i]);
        return;
    }
    int j = i - PB_ELEMS;
    if (j < xtotal) { g_x16[j] = __float2half_rn(x[j]); return; }
    j -= xtotal;
    if (j < 128 * 256) { split_h(l1w[j], g_w1h[j], g_w1l[j]); return; }
    j -= 128 * 256;
    if (j < 256 * 128) { split_h(l2w[j], g_w2h[j], g_w2l[j]); return; }
    j -= 256 * 128;
    if (j < n) { g_counts[j] = 0; g_cursor[j] = 0; }
}

// ---------------- CSR gather: 2 dest rows per warp (MLP x2) -> fp16 A rows ----------------
__global__ __launch_bounds__(256) void k_gather(int n) {
    int wp = (blockIdx.x * blockDim.x + threadIdx.x) >> 5;   // warp id = row pair
    int lane = threadIdx.x & 31;
    int w0 = wp * 2, w1 = wp * 2 + 1;
    if (w0 >= n) return;
    bool has1 = (w1 < n);
    const uint4* __restrict__ hn = (const uint4*)g_hn;

    float a0[8], a1[8];
    {
        uint4 v = hn[w0 * 32 + lane];
        const __half2* ph = (const __half2*)&v;
#pragma unroll
        for (int j = 0; j < 4; j++) {
            float2 f = __half22float2(ph[j]);
            a0[2 * j] = f.x; a0[2 * j + 1] = f.y;
        }
    }
    if (has1) {
        uint4 v = hn[w1 * 32 + lane];
        const __half2* ph = (const __half2*)&v;
#pragma unroll
        for (int j = 0; j < 4; j++) {
            float2 f = __half22float2(ph[j]);
            a1[2 * j] = f.x; a1[2 * j + 1] = f.y;
        }
    } else {
#pragma unroll
        for (int j = 0; j < 8; j++) a1[j] = 0.f;
    }

    int beg0 = g_rowptr[w0], end0 = g_rowptr[w0 + 1];
    int beg1 = has1 ? g_rowptr[w1] : 0, end1 = has1 ? g_rowptr[w1 + 1] : 0;

    // interleaved dual-row main loop: 4 neighbors of each row in flight (8 loads)
    int i0 = beg0, i1 = beg1;
    while (i0 + 3 < end0 && i1 + 3 < end1) {
        int s00 = g_csr[i0], s01 = g_csr[i0 + 1], s02 = g_csr[i0 + 2], s03 = g_csr[i0 + 3];
        int s10 = g_csr[i1], s11 = g_csr[i1 + 1], s12 = g_csr[i1 + 2], s13 = g_csr[i1 + 3];
        uint4 p0 = hn[s00 * 32 + lane], p1 = hn[s01 * 32 + lane];
        uint4 p2 = hn[s02 * 32 + lane], p3 = hn[s03 * 32 + lane];
        uint4 q0 = hn[s10 * 32 + lane], q1 = hn[s11 * 32 + lane];
        uint4 q2 = hn[s12 * 32 + lane], q3 = hn[s13 * 32 + lane];
        const __half2 *pp0 = (const __half2*)&p0, *pp1 = (const __half2*)&p1;
        const __half2 *pp2 = (const __half2*)&p2, *pp3 = (const __half2*)&p3;
        const __half2 *qq0 = (const __half2*)&q0, *qq1 = (const __half2*)&q1;
        const __half2 *qq2 = (const __half2*)&q2, *qq3 = (const __half2*)&q3;
#pragma unroll
        for (int j = 0; j < 4; j++) {
            float2 f0 = __half22float2(pp0[j]), f1 = __half22float2(pp1[j]);
            float2 f2 = __half22float2(pp2[j]), f3 = __half22float2(pp3[j]);
            a0[2 * j]     += (f0.x + f1.x) + (f2.x + f3.x);
            a0[2 * j + 1] += (f0.y + f1.y) + (f2.y + f3.y);
            float2 g0 = __half22float2(qq0[j]), g1 = __half22float2(qq1[j]);
            float2 g2 = __half22float2(qq2[j]), g3 = __half22float2(qq3[j]);
            a1[2 * j]     += (g0.x + g1.x) + (g2.x + g3.x);
            a1[2 * j + 1] += (g0.y + g1.y) + (g2.y + g3.y);
        }
        i0 += 4; i1 += 4;
    }
    // row-0 remainder (4-wide then scalar)
    for (; i0 + 3 < end0; i0 += 4) {
        int s0 = g_csr[i0], s1 = g_csr[i0 + 1], s2 = g_csr[i0 + 2], s3 = g_csr[i0 + 3];
        uint4 p = hn[s0 * 32 + lane], q = hn[s1 * 32 + lane];
        uint4 r = hn[s2 * 32 + lane], t = hn[s3 * 32 + lane];
        const __half2 *pp = (const __half2*)&p, *qq = (const __half2*)&q;
        const __half2 *rr = (const __half2*)&r, *tt = (const __half2*)&t;
#pragma unroll
        for (int j = 0; j < 4; j++) {
            float2 fp = __half22float2(pp[j]), fq = __half22float2(qq[j]);
            float2 fr = __half22float2(rr[j]), ft = __half22float2(tt[j]);
            a0[2 * j]     += (fp.x + fq.x) + (fr.x + ft.x);
            a0[2 * j + 1] += (fp.y + fq.y) + (fr.y + ft.y);
        }
    }
    for (; i0 < end0; i0++) {
        uint4 p = hn[g_csr[i0] * 32 + lane];
        const __half2* pp = (const __half2*)&p;
#pragma unroll
        for (int j = 0; j < 4; j++) {
            float2 fp = __half22float2(pp[j]);
            a0[2 * j] += fp.x; a0[2 * j + 1] += fp.y;
        }
    }
    // row-1 remainder
    for (; i1 + 3 < end1; i1 += 4) {
        int s0 = g_csr[i1], s1 = g_csr[i1 + 1], s2 = g_csr[i1 + 2], s3 = g_csr[i1 + 3];
        uint4 p = hn[s0 * 32 + lane], q = hn[s1 * 32 + lane];
        uint4 r = hn[s2 * 32 + lane], t = hn[s3 * 32 + lane];
        const __half2 *pp = (const __half2*)&p, *qq = (const __half2*)&q;
        const __half2 *rr = (const __half2*)&r, *tt = (const __half2*)&t;
#pragma unroll
        for (int j = 0; j < 4; j++) {
            float2 fp = __half22float2(pp[j]), fq = __half22float2(qq[j]);
            float2 fr = __half22float2(rr[j]), ft = __half22float2(tt[j]);
            a1[2 * j]     += (fp.x + fq.x) + (fr.x + ft.x);
            a1[2 * j + 1] += (fp.y + fq.y) + (fr.y + ft.y);
        }
    }
    for (; i1 < end1; i1++) {
        uint4 p = hn[g_csr[i1] * 32 + lane];
        const __half2* pp = (const __half2*)&p;
#pragma unroll
        for (int j = 0; j < 4; j++) {
            float2 fp = __half22float2(pp[j]);
            a1[2 * j] += fp.x; a1[2 * j + 1] += fp.y;
        }
    }

    {
        float dc = g_dis[w0];
        size_t ro = (size_t)w0 * 512 + lane * 8;
        __half hh[8];
#pragma unroll
        for (int j = 0; j < 8; j++) hh[j] = __float2half_rn(a0[j] * dc);
        *(uint4*)&g_a[ro] = *(uint4*)hh;
    }
    if (has1) {
        float dc = g_dis[w1];
        size_t ro = (size_t)w1 * 512 + lane * 8;
        __half hh[8];
#pragma unroll
        for (int j = 0; j < 8; j++) hh[j] = __float2half_rn(a1[j] * dc);
        *(uint4*)&g_a[ro] = *(uint4*)hh;
    }
}

// ---------------- layer GEMM: fp16 2-pass, 128m x 256n, K=512 (8x64) ----------------
#define STAGE 81920u
#define SMTOT 163840
__global__ __launch_bounds__(256, 1) void k_mma(int layer, int nvalid) {
    extern __shared__ char smem[];
    uint32_t sb = s2u(smem);
    const int tid = threadIdx.x, lane = tid & 31, wid = tid >> 5;
    const int T = blockIdx.x;

    const __half* __restrict__ Ag = g_a + (size_t)T * 128 * 512;
    const __half* __restrict__ Bgh = g_bh + (size_t)layer * 512 * 256;
    const __half* __restrict__ Bgl = g_bl + (size_t)layer * 512 * 256;

    auto load_chunk = [&](int c, int st) {
        uint32_t s0 = sb + st * STAGE;
#pragma unroll
        for (int i = 0; i < 4; i++) {
            int e = tid + i * 256;
            int m = e >> 3, kc = e & 7;
            uint32_t da = (uint32_t)(m * 128 + ((kc ^ (m & 7)) << 4));
            cp16(s0 + da, Ag + (size_t)m * 512 + c * 64 + kc * 8);
        }
#pragma unroll
        for (int i = 0; i < 8; i++) {
            int e = tid + i * 256;
            int k = e >> 5, ncol = e & 31;
            int nhalf = ncol >> 4, nc = ncol & 15;
            uint32_t db = (uint32_t)(nhalf * 16384 + k * 256 + ((nc ^ (k & 7)) << 4));
            size_t src = (size_t)(c * 64 + k) * 256 + nhalf * 128 + nc * 8;
            cp16(s0 + 16384 + db, Bgh + src);
            cp16(s0 + 49152 + db, Bgl + src);
        }
        CP_COMMIT();
    };

    float acc[4][8][4];
#pragma unroll
    for (int i = 0; i < 4; i++)
#pragma unroll
        for (int j = 0; j < 8; j++)
#pragma unroll
            for (int q = 0; q < 4; q++) acc[i][j][q] = 0.f;

    const int wm = (wid & 1) * 64;
    const int wng = (wid >> 1) * 64;
    const uint32_t nhb = (uint32_t)((wng >> 7) * 16384);
    const int ncb = (wng & 127) >> 3;

    auto compute = [&](uint32_t s0) {
        uint32_t sa = s0, sbh = s0 + 16384, sbl = s0 + 49152;
#pragma unroll
        for (int kq = 0; kq < 4; kq++) {
            uint32_t ar[4][4], bh[4][4], bl[4][4];
#pragma unroll
            for (int mi = 0; mi < 4; mi++) {
                int m = wm + mi * 16 + (lane & 15);
                int kcc = kq * 2 + (lane >> 4);
                uint32_t ad = (uint32_t)(m * 128 + ((kcc ^ (m & 7)) << 4));
                LDSM4(ar[mi][0], ar[mi][1], ar[mi][2], ar[mi][3], sa + ad);
            }
#pragma unroll
            for (int nj = 0; nj < 4; nj++) {
                int kr = kq * 16 + (lane & 15);
                int nc = ncb + nj * 2 + (lane >> 4);
                uint32_t bd = nhb + (uint32_t)(kr * 256 + ((nc ^ (kr & 7)) << 4));
                LDSM4T(bh[nj][0], bh[nj][1], bh[nj][2], bh[nj][3], sbh + bd);
                LDSM4T(bl[nj][0], bl[nj][1], bl[nj][2], bl[nj][3], sbl + bd);
            }
#pragma unroll
            for (int mi = 0; mi < 4; mi++)
#pragma unroll
                for (int nt = 0; nt < 8; nt++) {
                    int nj = nt >> 1, pq = (nt & 1) * 2;
                    MMA_F16(acc[mi][nt], ar[mi], bh[nj][pq], bh[nj][pq + 1]);
                    MMA_F16(acc[mi][nt], ar[mi], bl[nj][pq], bl[nj][pq + 1]);
                }
        }
    };

    load_chunk(0, 0);
    for (int ch = 0; ch < 8; ch++) {
        if (ch < 7) { load_chunk(ch + 1, (ch + 1) & 1); CP_WAIT(1); }
        else        { CP_WAIT(0); }
        __syncthreads();
        compute(sb + (ch & 1) * STAGE);
        __syncthreads();
    }

    float s = 0.f, ss = 0.f;
    int rbase = T * 128 + wm + (lane >> 2);
    int cbase = wng + (lane & 3) * 2;
#pragma unroll
    for (int mi = 0; mi < 4; mi++) {
        int r0 = rbase + mi * 16;
        int r1 = r0 + 8;
        bool v0 = r0 < nvalid, v1 = r1 < nvalid;
#pragma unroll
        for (int nt = 0; nt < 8; nt++) {
            int col = cbase + nt * 8;
            if (v0) {
                float2 p = make_float2(acc[mi][nt][0], acc[mi][nt][1]);
                *(float2*)&g_ha[(size_t)r0 * DH + col] = p;
                s += p.x + p.y; ss += p.x * p.x + p.y * p.y;
            }
            if (v1) {
                float2 p = make_float2(acc[mi][nt][2], acc[mi][nt][3]);
                *(float2*)&g_ha[(size_t)r1 * DH + col] = p;
                s += p.x + p.y; ss += p.x * p.x + p.y * p.y;
            }
        }
    }
#pragma unroll
    for (int o = 16; o > 0; o >>= 1) {
        s += __shfl_xor_sync(0xffffffffu, s, o);
        ss += __shfl_xor_sync(0xffffffffu, ss, o);
    }
    __syncthreads();
    float* red = (float*)smem;
    if (lane == 0) { red[wid] = s; red[8 + wid] = ss; }
    __syncthreads();
    if (tid == 0) {
        float a = 0.f, b = 0.f;
#pragma unroll
        for (int i = 0; i < 8; i++) { a += red[i]; b += red[8 + i]; }
        g_part[T] = a; g_part2[T] = b;
    }
}

// ---------------- lin1: fp16 2-pass, 128m x 256n, K=128 (2x64) ----------------
__global__ __launch_bounds__(256, 1) void k_lin1(const float* __restrict__ bias, int nvalid) {
    extern __shared__ char smem[];
    uint32_t sb = s2u(smem);
    const int tid = threadIdx.x, lane = tid & 31, wid = tid >> 5;
    const int T = blockIdx.x;

    auto load_chunk = [&](int c, int st) {
        uint32_t s0 = sb + st * STAGE;
#pragma unroll
        for (int i = 0; i < 4; i++) {
            int e = tid + i * 256;
            int m = e >> 3, kc = e & 7;
            uint32_t da = (uint32_t)(m * 128 + ((kc ^ (m & 7)) << 4));
            cp16(s0 + da, g_x16 + (size_t)(T * 128 + m) * 128 + c * 64 + kc * 8);
        }
#pragma unroll
        for (int i = 0; i < 8; i++) {
            int e = tid + i * 256;
            int k = e >> 5, ncol = e & 31;
            int nhalf = ncol >> 4, nc = ncol & 15;
            uint32_t db = (uint32_t)(nhalf * 16384 + k * 256 + ((nc ^ (k & 7)) << 4));
            size_t src = (size_t)(c * 64 + k) * 256 + nhalf * 128 + nc * 8;
            cp16(s0 + 16384 + db, g_w1h + src);
            cp16(s0 + 49152 + db, g_w1l + src);
        }
        CP_COMMIT();
    };

    float acc[4][8][4];
#pragma unroll
    for (int i = 0; i < 4; i++)
#pragma unroll
        for (int j = 0; j < 8; j++)
#pragma unroll
            for (int q = 0; q < 4; q++) acc[i][j][q] = 0.f;

    const int wm = (wid & 1) * 64;
    const int wng = (wid >> 1) * 64;
    const uint32_t nhb = (uint32_t)((wng >> 7) * 16384);
    const int ncb = (wng & 127) >> 3;

    auto compute = [&](uint32_t s0) {
        uint32_t sa = s0, sbh = s0 + 16384, sbl = s0 + 49152;
#pragma unroll
        for (int kq = 0; kq < 4; kq++) {
            uint32_t ar[4][4], bh[4][4], bl[4][4];
#pragma unroll
            for (int mi = 0; mi < 4; mi++) {
                int m = wm + mi * 16 + (lane & 15);
                int kcc = kq * 2 + (lane >> 4);
                uint32_t ad = (uint32_t)(m * 128 + ((kcc ^ (m & 7)) << 4));
                LDSM4(ar[mi][0], ar[mi][1], ar[mi][2], ar[mi][3], sa + ad);
            }
#pragma unroll
            for (int nj = 0; nj < 4; nj++) {
                int kr = kq * 16 + (lane & 15);
                int nc = ncb + nj * 2 + (lane >> 4);
                uint32_t bd = nhb + (uint32_t)(kr * 256 + ((nc ^ (kr & 7)) << 4));
                LDSM4T(bh[nj][0], bh[nj][1], bh[nj][2], bh[nj][3], sbh + bd);
                LDSM4T(bl[nj][0], bl[nj][1], bl[nj][2], bl[nj][3], sbl + bd);
            }
#pragma unroll
            for (int mi = 0; mi < 4; mi++)
#pragma unroll
                for (int nt = 0; nt < 8; nt++) {
                    int nj = nt >> 1, pq = (nt & 1) * 2;
                    MMA_F16(acc[mi][nt], ar[mi], bh[nj][pq], bh[nj][pq + 1]);
                    MMA_F16(acc[mi][nt], ar[mi], bl[nj][pq], bl[nj][pq + 1]);
                }
        }
    };

    load_chunk(0, 0);
    load_chunk(1, 1);
    CP_WAIT(1);
    __syncthreads();
    compute(sb);
    __syncthreads();
    CP_WAIT(0);
    __syncthreads();
    compute(sb + STAGE);

    int rbase = T * 128 + wm + (lane >> 2);
    int cbase = wng + (lane & 3) * 2;
#pragma unroll
    for (int mi = 0; mi < 4; mi++) {
        int r0 = rbase + mi * 16;
        int r1 = r0 + 8;
        float d0 = (r0 < nvalid) ? g_dis[r0] : 0.f;
        float d1 = (r1 < nvalid) ? g_dis[r1] : 0.f;
#pragma unroll
        for (int nt = 0; nt < 8; nt++) {
            int col = cbase + nt * 8;
            float2 bb = *(const float2*)&bias[col];
            float v0 = fmaxf(acc[mi][nt][0] + bb.x, 0.f);
            float v1 = fmaxf(acc[mi][nt][1] + bb.y, 0.f);
            *(__half2*)&g_a[(size_t)r0 * 512 + 256 + col] = __floats2half2_rn(v0, v1);
            if (r0 < nvalid)
                *(__half2*)&g_hn[(size_t)r0 * DH + col] = __floats2half2_rn(v0 * d0, v1 * d0);
            float v2 = fmaxf(acc[mi][nt][2] + bb.x, 0.f);
            float v3 = fmaxf(acc[mi][nt][3] + bb.y, 0.f);
            *(__half2*)&g_a[(size_t)r1 * 512 + 256 + col] = __floats2half2_rn(v2, v3);
            if (r1 < nvalid)
                *(__half2*)&g_hn[(size_t)r1 * DH + col] = __floats2half2_rn(v2 * d1, v3 * d1);
        }
    }
}

// ---------------- lin2: fp16 2-pass, 256m x 128n, K=256 (4x64) ----------------
#define L2STAGE 65536u
#define L2SMTOT 131072
__global__ __launch_bounds__(256, 1) void k_lin2(const float* __restrict__ bias,
                                                 float* __restrict__ out, int nvalid) {
    extern __shared__ char smem[];
    uint32_t sb = s2u(smem);
    const int tid = threadIdx.x, lane = tid & 31, wid = tid >> 5;
    const int T = blockIdx.x;

    auto load_chunk = [&](int c, int st) {
        uint32_t s0 = sb + st * L2STAGE;
#pragma unroll
        for (int i = 0; i < 8; i++) {
            int e = tid + i * 256;
            int m = e >> 3, kc = e & 7;
            uint32_t da = (uint32_t)(m * 128 + ((kc ^ (m & 7)) << 4));
            cp16(s0 + da, g_hn + (size_t)(T * 256 + m) * DH + c * 64 + kc * 8);
        }
#pragma unroll
        for (int i = 0; i < 4; i++) {
            int e = tid + i * 256;
            int k = e >> 4, nc = e & 15;
            uint32_t db = (uint32_t)(k * 256 + ((nc ^ (k & 7)) << 4));
            size_t src = (size_t)(c * 64 + k) * 128 + nc * 8;
            cp16(s0 + 32768 + db, g_w2h + src);
            cp16(s0 + 49152 + db, g_w2l + src);
        }
        CP_COMMIT();
    };

    float acc[4][8][4];
#pragma unroll
    for (int i = 0; i < 4; i++)
#pragma unroll
        for (int j = 0; j < 8; j++)
#pragma unroll
            for (int q = 0; q < 4; q++) acc[i][j][q] = 0.f;

    const int wm = (wid & 3) * 64;
    const int wn = (wid >> 2) * 64;
    const int ncb = wn >> 3;

    auto compute = [&](uint32_t s0) {
        uint32_t sa = s0, sbh = s0 + 32768, sbl = s0 + 49152;
#pragma unroll
        for (int kq = 0; kq < 4; kq++) {
            uint32_t ar[4][4], bh[4][4], bl[4][4];
#pragma unroll
            for (int mi = 0; mi < 4; mi++) {
                int m = wm + mi * 16 + (lane & 15);
                int kcc = kq * 2 + (lane >> 4);
                uint32_t ad = (uint32_t)(m * 128 + ((kcc ^ (m & 7)) << 4));
                LDSM4(ar[mi][0], ar[mi][1], ar[mi][2], ar[mi][3], sa + ad);
            }
#pragma unroll
            for (int nj = 0; nj < 4; nj++) {
                int kr = kq * 16 + (lane & 15);
                int nc = ncb + nj * 2 + (lane >> 4);
                uint32_t bd = (uint32_t)(kr * 256 + ((nc ^ (kr & 7)) << 4));
                LDSM4T(bh[nj][0], bh[nj][1], bh[nj][2], bh[nj][3], sbh + bd);
                LDSM4T(bl[nj][0], bl[nj][1], bl[nj][2], bl[nj][3], sbl + bd);
            }
#pragma unroll
            for (int mi = 0; mi < 4; mi++)
#pragma unroll
                for (int nt = 0; nt < 8; nt++) {
                    int nj = nt >> 1, pq = (nt & 1) * 2;
                    MMA_F16(acc[mi][nt], ar[mi], bh[nj][pq], bh[nj][pq + 1]);
                    MMA_F16(acc[mi][nt], ar[mi], bl[nj][pq], bl[nj][pq + 1]);
                }
        }
    };

    load_chunk(0, 0);
    for (int ch = 0; ch < 4; ch++) {
        if (ch < 3) { load_chunk(ch + 1, (ch + 1) & 1); CP_WAIT(1); }
        else        { CP_WAIT(0); }
        __syncthreads();
        compute(sb + (ch & 1) * L2STAGE);
        __syncthreads();
    }

    int rbase = T * 256 + wm + (lane >> 2);
    int cbase = wn + (lane & 3) * 2;
#pragma unroll
    for (int mi = 0; mi < 4; mi++) {
        int r0 = rbase + mi * 16;
        int r1 = r0 + 8;
        bool v0 = r0 < nvalid, v1 = r1 < nvalid;
#pragma unroll
        for (int nt = 0; nt < 8; nt++) {
            int col = cbase + nt * 8;
            float2 bb = *(const float2*)&bias[col];
            if (v0) {
                float2 p = make_float2(fmaxf(acc[mi][nt][0] + bb.x, 0.f),
                                       fmaxf(acc[mi][nt][1] + bb.y, 0.f));
                *(float2*)&out[(size_t)r0 * 128 + col] = p;
            }
            if (v1) {
                float2 p = make_float2(fmaxf(acc[mi][nt][2] + bb.x, 0.f),
                                       fmaxf(acc[mi][nt][3] + bb.y, 0.f));
                *(float2*)&out[(size_t)r1 * 128 + col] = p;
            }
        }
    }
}

// ---------------- layernorm: finalize + normalize+relu (+dis prescale) ----------------
__global__ __launch_bounds__(256) void k_norm(const float* __restrict__ gamma,
                                              const float* __restrict__ beta,
                                              int total4, int nparts, float invcnt, int scale_dis) {
    __shared__ float sred[512];
    __shared__ float s_scale[256], s_shift[256];
    const int tid = threadIdx.x;

    float s = 0.f, ss = 0.f;
    for (int i = tid; i < nparts; i += 256) { s += g_part[i]; ss += g_part2[i]; }
    sred[tid] = s; sred[256 + tid] = ss;
    __syncthreads();
    for (int o = 128; o > 0; o >>= 1) {
        if (tid < o) { sred[tid] += sred[tid + o]; sred[256 + tid] += sred[256 + tid + o]; }
        __syncthreads();
    }
    float mu = sred[0] * invcnt;
    float var = fmaxf(sred[256] * invcnt - mu * mu, 0.f);
    float inv = 1.0f / (sqrtf(var) + 1e-5f);
    float gch = gamma[tid] * inv;
    s_scale[tid] = gch;
    s_shift[tid] = beta[tid] - mu * gch;
    __syncthreads();

    int stride = gridDim.x * 256;
    for (int i = blockIdx.x * 256 + tid; i < total4; i += stride) {
        float4 v = ((const float4*)g_ha)[i];
        int f = (i * 4) & 255;
        int node = i >> 6;
        float d = scale_dis ? g_dis[node] : 1.0f;
        float4 g = *(float4*)&s_scale[f];
        float4 b = *(float4*)&s_shift[f];
        v.x = fmaxf(fmaf(v.x, g.x, b.x), 0.f) * d;
        v.y = fmaxf(fmaf(v.y, g.y, b.y), 0.f) * d;
        v.z = fmaxf(fmaf(v.z, g.z, b.z), 0.f) * d;
        v.w = fmaxf(fmaf(v.w, g.w, b.w), 0.f) * d;
        __half2* dst = (__half2*)&g_hn[(size_t)i * 4];
        dst[0] = __floats2half2_rn(v.x, v.y);
        dst[1] = __floats2half2_rn(v.z, v.w);
    }
}

// ---------------- launch ----------------
extern "C" void kernel_launch(void* const* d_in, const int* in_sizes, int n_in,
                              void* d_out, int out_size) {
    const float* x      = (const float*)d_in[0];
    const int*   ei     = (const int*)d_in[1];
    const float* lin1_w = (const float*)d_in[2];
    const float* lin1_b = (const float*)d_in[3];
    const float* w1     = (const float*)d_in[4];
    const float* w2     = (const float*)d_in[5];
    const float* gamma  = (const float*)d_in[6];
    const float* betab  = (const float*)d_in[7];
    const float* lin2_w = (const float*)d_in[8];
    const float* lin2_b = (const float*)d_in[9];
    float* out = (float*)d_out;

    int N = in_sizes[0] / 128;
    int E = in_sizes[1] / 2;
    const int* row = ei;
    const int* col = ei + E;

    int Mt = (N + 127) / 128;
    int Mt2 = (N + 255) / 256;
    int total4 = N * (DH / 4);
    float invcnt = 1.0f / ((float)N * (float)DH);
    int xtotal = N * 128;
    int prep_total = PB_ELEMS + xtotal + 128 * 256 + 256 * 128 + N;
    int npairs = (N + 1) / 2;

    static int smem_set = 0;
    if (!smem_set) {
        cudaFuncSetAttribute(k_mma, cudaFuncAttributeMaxDynamicSharedMemorySize, SMTOT);
        cudaFuncSetAttribute(k_lin1, cudaFuncAttributeMaxDynamicSharedMemorySize, SMTOT);
        cudaFuncSetAttribute(k_lin2, cudaFuncAttributeMaxDynamicSharedMemorySize, L2SMTOT);
        smem_set = 1;
    }

    k_prep_all<<<(prep_total + 255) / 256, 256>>>(w1, w2, x, xtotal, lin1_w, lin2_w, N);
    k_count<<<(E + 255) / 256, 256>>>(col, E);
    k_scan<<<1, 1024>>>(N, E);
    k_scatter<<<(E + 255) / 256, 256>>>(row, col, E);

    k_lin1<<<Mt, 256, SMTOT>>>(lin1_b, N);

    for (int l = 0; l < NL; l++) {
        k_gather<<<(npairs * 32 + 255) / 256, 256>>>(N);
        k_mma<<<Mt, 256, SMTOT>>>(l, N);
        k_norm<<<1184, 256>>>(gamma + l * DH, betab + l * DH, total4, Mt, invcnt,
                              (l < NL - 1) ? 1 : 0);
    }

    k_lin2<<<Mt2, 256, L2SMTOT>>>(lin2_b, out, N);
}

// round 17
// speedup vs baseline: 1.1084x; 1.0436x over previous
#include <cuda_runtime.h>
#include <cuda_fp16.h>
#include <math.h>
#include <stdint.h>

#define NN 50000
#define EE 800000
#define DH 256
#define NL 8
#define NTILES ((NN + 127) / 128)        // 391
#define NPAD (NTILES * 128)              // 50048
#define NT2 ((NN + 255) / 256)           // 196
#define NPAD2 (NT2 * 256)                // 50176

// ---------------- scratch ----------------
__device__ float g_ha[NN * DH];                                  // fp32 h_out (per-layer)
__device__ __align__(16) __half g_hn[(size_t)NPAD2 * DH];        // fp16 dis*relu(norm(h)) / dis*x0
__device__ __align__(16) __half g_a[(size_t)NPAD * 512];         // fp16 A [node][k] k<256 agg, k>=256 x0
__device__ __align__(16) __half g_bh[(size_t)NL * 512 * 256];    // B' hi
__device__ __align__(16) __half g_bl[(size_t)NL * 512 * 256];    // B' lo
__device__ __align__(16) __half g_x16[(size_t)NPAD * 128];       // fp16 x
__device__ __align__(16) __half g_w1h[128 * 256], g_w1l[128 * 256];
__device__ __align__(16) __half g_w2h[256 * 128], g_w2l[256 * 128];
__device__ float g_dis[NN];
__device__ int   g_counts[NN];
__device__ int   g_cursor[NN];
__device__ int   g_rowptr[NN + 1];
__device__ int   g_csr[EE];
__device__ float g_part[NTILES * 2 + 8];
__device__ float g_part2[NTILES * 2 + 8];

// ---------------- helpers ----------------
__device__ __forceinline__ uint32_t s2u(const void* p) {
    uint32_t a;
    asm("{ .reg .u64 t; cvta.to.shared.u64 t, %1; cvt.u32.u64 %0, t; }" : "=r"(a) : "l"(p));
    return a;
}
__device__ __forceinline__ void cp16(uint32_t dst, const void* src) {
    asm volatile("cp.async.cg.shared.global [%0], [%1], 16;" :: "r"(dst), "l"(src) : "memory");
}
#define CP_COMMIT() asm volatile("cp.async.commit_group;" ::: "memory")
#define CP_WAIT(n)  asm volatile("cp.async.wait_group %0;" :: "n"(n) : "memory")

#define LDSM4(r0,r1,r2,r3,a) \
    asm volatile("ldmatrix.sync.aligned.m8n8.x4.shared.b16 {%0,%1,%2,%3}, [%4];" \
                 : "=r"(r0),"=r"(r1),"=r"(r2),"=r"(r3) : "r"(a))
#define LDSM4T(r0,r1,r2,r3,a) \
    asm volatile("ldmatrix.sync.aligned.m8n8.x4.trans.shared.b16 {%0,%1,%2,%3}, [%4];" \
                 : "=r"(r0),"=r"(r1),"=r"(r2),"=r"(r3) : "r"(a))
#define MMA_F16(c,a,b0,b1) \
    asm volatile("mma.sync.aligned.m16n8k16.row.col.f32.f16.f16.f32 " \
                 "{%0,%1,%2,%3}, {%4,%5,%6,%7}, {%8,%9}, {%0,%1,%2,%3};" \
                 : "+f"((c)[0]),"+f"((c)[1]),"+f"((c)[2]),"+f"((c)[3]) \
                 : "r"((a)[0]),"r"((a)[1]),"r"((a)[2]),"r"((a)[3]),"r"(b0),"r"(b1))

__device__ __forceinline__ void split_h(float v, __half& h, __half& l) {
    h = __float2half_rn(v);
    l = __float2half_rn(v - __half2float(h));
}

// ---------------- graph preprocessing ----------------
__global__ void k_count(const int* __restrict__ col, int E) {
    int e = blockIdx.x * blockDim.x + threadIdx.x;
    if (e < E) atomicAdd(&g_counts[col[e]], 1);
}
__global__ void k_scan(int n, int E) {
    __shared__ int sh[1024];
    int tid = threadIdx.x;
    int C = (n + 1023) >> 10;
    int base = tid * C;
    int s = 0;
    for (int i = 0; i < C; i++) { int idx = base + i; if (idx < n) s += g_counts[idx]; }
    sh[tid] = s; __syncthreads();
    for (int off = 1; off < 1024; off <<= 1) {
        int v = (tid >= off) ? sh[tid - off] : 0;
        __syncthreads();
        sh[tid] += v;
        __syncthreads();
    }
    int run = (tid > 0) ? sh[tid - 1] : 0;
    for (int i = 0; i < C; i++) {
        int idx = base + i;
        if (idx < n) {
            g_rowptr[idx] = run;
            int c = g_counts[idx];
            run += c;
            g_dis[idx] = rsqrtf((float)(c + 1));
        }
    }
    if (tid == 0) g_rowptr[n] = E;
}
__global__ void k_scatter(const int* __restrict__ row, const int* __restrict__ col, int E) {
    int e = blockIdx.x * blockDim.x + threadIdx.x;
    if (e < E) {
        int c = col[e];
        int p = g_rowptr[c] + atomicAdd(&g_cursor[c], 1);
        g_csr[p] = row[e];
    }
}

// ---------------- unified prep ----------------
#define PB_ELEMS (NL * 512 * 256)
__global__ void k_prep_all(const float* __restrict__ w1, const float* __restrict__ w2,
                           const float* __restrict__ x, int xtotal,
                           const float* __restrict__ l1w, const float* __restrict__ l2w,
                           int n) {
    int i = blockIdx.x * blockDim.x + threadIdx.x;
    if (i < PB_ELEMS) {
        int nn = i & 255;
        int k = (i >> 8) & 511;
        int l = i >> 17;
        float beta = logf(1.0f / (float)(l + 1) + 1.0f);
        float v = (k < 256) ? w1[(l << 16) + (k << 8) + nn]
                            : w2[(l << 16) + ((k - 256) << 8) + nn];
        float val = 0.5f * beta * v;
        if (k == nn || k == nn + 256) val += 0.5f * (1.0f - beta);
        split_h(val, g_bh[i], g_bl[i]);
        return;
    }
    int j = i - PB_ELEMS;
    if (j < xtotal) { g_x16[j] = __float2half_rn(x[j]); return; }
    j -= xtotal;
    if (j < 128 * 256) { split_h(l1w[j], g_w1h[j], g_w1l[j]); return; }
    j -= 128 * 256;
    if (j < 256 * 128) { split_h(l2w[j], g_w2h[j], g_w2l[j]); return; }
    j -= 256 * 128;
    if (j < n) { g_counts[j] = 0; g_cursor[j] = 0; }
}

// ---------------- CSR gather: 2 dest rows per warp -> fp16 A rows ----------------
__global__ __launch_bounds__(256) void k_gather(int n) {
    int wp = (blockIdx.x * blockDim.x + threadIdx.x) >> 5;
    int lane = threadIdx.x & 31;
    int w0 = wp * 2, w1 = wp * 2 + 1;
    if (w0 >= n) return;
    bool has1 = (w1 < n);
    const uint4* __restrict__ hn = (const uint4*)g_hn;

    float a0[8], a1[8];
    {
        uint4 v = hn[w0 * 32 + lane];
        const __half2* ph = (const __half2*)&v;
#pragma unroll
        for (int j = 0; j < 4; j++) {
            float2 f = __half22float2(ph[j]);
            a0[2 * j] = f.x; a0[2 * j + 1] = f.y;
        }
    }
    if (has1) {
        uint4 v = hn[w1 * 32 + lane];
        const __half2* ph = (const __half2*)&v;
#pragma unroll
        for (int j = 0; j < 4; j++) {
            float2 f = __half22float2(ph[j]);
            a1[2 * j] = f.x; a1[2 * j + 1] = f.y;
        }
    } else {
#pragma unroll
        for (int j = 0; j < 8; j++) a1[j] = 0.f;
    }

    int beg0 = g_rowptr[w0], end0 = g_rowptr[w0 + 1];
    int beg1 = has1 ? g_rowptr[w1] : 0, end1 = has1 ? g_rowptr[w1 + 1] : 0;

    int i0 = beg0, i1 = beg1;
    while (i0 + 3 < end0 && i1 + 3 < end1) {
        int s00 = g_csr[i0], s01 = g_csr[i0 + 1], s02 = g_csr[i0 + 2], s03 = g_csr[i0 + 3];
        int s10 = g_csr[i1], s11 = g_csr[i1 + 1], s12 = g_csr[i1 + 2], s13 = g_csr[i1 + 3];
        uint4 p0 = hn[s00 * 32 + lane], p1 = hn[s01 * 32 + lane];
        uint4 p2 = hn[s02 * 32 + lane], p3 = hn[s03 * 32 + lane];
        uint4 q0 = hn[s10 * 32 + lane], q1 = hn[s11 * 32 + lane];
        uint4 q2 = hn[s12 * 32 + lane], q3 = hn[s13 * 32 + lane];
        const __half2 *pp0 = (const __half2*)&p0, *pp1 = (const __half2*)&p1;
        const __half2 *pp2 = (const __half2*)&p2, *pp3 = (const __half2*)&p3;
        const __half2 *qq0 = (const __half2*)&q0, *qq1 = (const __half2*)&q1;
        const __half2 *qq2 = (const __half2*)&q2, *qq3 = (const __half2*)&q3;
#pragma unroll
        for (int j = 0; j < 4; j++) {
            float2 f0 = __half22float2(pp0[j]), f1 = __half22float2(pp1[j]);
            float2 f2 = __half22float2(pp2[j]), f3 = __half22float2(pp3[j]);
            a0[2 * j]     += (f0.x + f1.x) + (f2.x + f3.x);
            a0[2 * j + 1] += (f0.y + f1.y) + (f2.y + f3.y);
            float2 g0 = __half22float2(qq0[j]), g1 = __half22float2(qq1[j]);
            float2 g2 = __half22float2(qq2[j]), g3 = __half22float2(qq3[j]);
            a1[2 * j]     += (g0.x + g1.x) + (g2.x + g3.x);
            a1[2 * j + 1] += (g0.y + g1.y) + (g2.y + g3.y);
        }
        i0 += 4; i1 += 4;
    }
    for (; i0 + 3 < end0; i0 += 4) {
        int s0 = g_csr[i0], s1 = g_csr[i0 + 1], s2 = g_csr[i0 + 2], s3 = g_csr[i0 + 3];
        uint4 p = hn[s0 * 32 + lane], q = hn[s1 * 32 + lane];
        uint4 r = hn[s2 * 32 + lane], t = hn[s3 * 32 + lane];
        const __half2 *pp = (const __half2*)&p, *qq = (const __half2*)&q;
        const __half2 *rr = (const __half2*)&r, *tt = (const __half2*)&t;
#pragma unroll
        for (int j = 0; j < 4; j++) {
            float2 fp = __half22float2(pp[j]), fq = __half22float2(qq[j]);
            float2 fr = __half22float2(rr[j]), ft = __half22float2(tt[j]);
            a0[2 * j]     += (fp.x + fq.x) + (fr.x + ft.x);
            a0[2 * j + 1] += (fp.y + fq.y) + (fr.y + ft.y);
        }
    }
    for (; i0 < end0; i0++) {
        uint4 p = hn[g_csr[i0] * 32 + lane];
        const __half2* pp = (const __half2*)&p;
#pragma unroll
        for (int j = 0; j < 4; j++) {
            float2 fp = __half22float2(pp[j]);
            a0[2 * j] += fp.x; a0[2 * j + 1] += fp.y;
        }
    }
    for (; i1 + 3 < end1; i1 += 4) {
        int s0 = g_csr[i1], s1 = g_csr[i1 + 1], s2 = g_csr[i1 + 2], s3 = g_csr[i1 + 3];
        uint4 p = hn[s0 * 32 + lane], q = hn[s1 * 32 + lane];
        uint4 r = hn[s2 * 32 + lane], t = hn[s3 * 32 + lane];
        const __half2 *pp = (const __half2*)&p, *qq = (const __half2*)&q;
        const __half2 *rr = (const __half2*)&r, *tt = (const __half2*)&t;
#pragma unroll
        for (int j = 0; j < 4; j++) {
            float2 fp = __half22float2(pp[j]), fq = __half22float2(qq[j]);
            float2 fr = __half22float2(rr[j]), ft = __half22float2(tt[j]);
            a1[2 * j]     += (fp.x + fq.x) + (fr.x + ft.x);
            a1[2 * j + 1] += (fp.y + fq.y) + (fr.y + ft.y);
        }
    }
    for (; i1 < end1; i1++) {
        uint4 p = hn[g_csr[i1] * 32 + lane];
        const __half2* pp = (const __half2*)&p;
#pragma unroll
        for (int j = 0; j < 4; j++) {
            float2 fp = __half22float2(pp[j]);
            a1[2 * j] += fp.x; a1[2 * j + 1] += fp.y;
        }
    }

    {
        float dc = g_dis[w0];
        size_t ro = (size_t)w0 * 512 + lane * 8;
        __half hh[8];
#pragma unroll
        for (int j = 0; j < 8; j++) hh[j] = __float2half_rn(a0[j] * dc);
        *(uint4*)&g_a[ro] = *(uint4*)hh;
    }
    if (has1) {
        float dc = g_dis[w1];
        size_t ro = (size_t)w1 * 512 + lane * 8;
        __half hh[8];
#pragma unroll
        for (int j = 0; j < 8; j++) hh[j] = __float2half_rn(a1[j] * dc);
        *(uint4*)&g_a[ro] = *(uint4*)hh;
    }
}

// ---------------- layer GEMM: fp16 2-pass, 128m x 128n CTA (grid (Mt,2)), 2 CTAs/SM ----------------
// 4 warps (128 threads) = 2m x 2n, warp tile 64x64. stage = A16K + Bh16K + Bl16K = 48KB, x2 = 96KB.
#define MSTAGE 49152u
#define MSMTOT 98304
__global__ __launch_bounds__(128, 2) void k_mma(int layer, int nvalid, int mtG) {
    extern __shared__ char smem[];
    uint32_t sb = s2u(smem);
    const int tid = threadIdx.x, lane = tid & 31, wid = tid >> 5;
    const int T = blockIdx.x, nh = blockIdx.y;

    const __half* __restrict__ Ag = g_a + (size_t)T * 128 * 512;
    const __half* __restrict__ Bgh = g_bh + (size_t)layer * 512 * 256 + nh * 128;
    const __half* __restrict__ Bgl = g_bl + (size_t)layer * 512 * 256 + nh * 128;

    auto load_chunk = [&](int c, int st) {
        uint32_t s0 = sb + st * MSTAGE;
        // A: 128m x 64k = 1024 x 16B
#pragma unroll
        for (int i = 0; i < 8; i++) {
            int e = tid + i * 128;
            int m = e >> 3, kc = e & 7;
            uint32_t da = (uint32_t)(m * 128 + ((kc ^ (m & 7)) << 4));
            cp16(s0 + da, Ag + (size_t)m * 512 + c * 64 + kc * 8);
        }
        // Bh/Bl: 64k x 128n = 1024 x 16B each (rows of 256B)
#pragma unroll
        for (int i = 0; i < 8; i++) {
            int e = tid + i * 128;
            int k = e >> 4, nc = e & 15;
            uint32_t db = (uint32_t)(k * 256 + ((nc ^ (k & 7)) << 4));
            size_t src = (size_t)(c * 64 + k) * 256 + nc * 8;
            cp16(s0 + 16384 + db, Bgh + src);
            cp16(s0 + 32768 + db, Bgl + src);
        }
        CP_COMMIT();
    };

    float acc[4][8][4];
#pragma unroll
    for (int i = 0; i < 4; i++)
#pragma unroll
        for (int j = 0; j < 8; j++)
#pragma unroll
            for (int q = 0; q < 4; q++) acc[i][j][q] = 0.f;

    const int wm = (wid & 1) * 64;
    const int wn = (wid >> 1) * 64;
    const int ncb = wn >> 3;

    auto compute = [&](uint32_t s0) {
        uint32_t sa = s0, sbh = s0 + 16384, sbl = s0 + 32768;
#pragma unroll
        for (int kq = 0; kq < 4; kq++) {
            uint32_t ar[4][4], bh[4][4], bl[4][4];
#pragma unroll
            for (int mi = 0; mi < 4; mi++) {
                int m = wm + mi * 16 + (lane & 15);
                int kcc = kq * 2 + (lane >> 4);
                uint32_t ad = (uint32_t)(m * 128 + ((kcc ^ (m & 7)) << 4));
                LDSM4(ar[mi][0], ar[mi][1], ar[mi][2], ar[mi][3], sa + ad);
            }
#pragma unroll
            for (int nj = 0; nj < 4; nj++) {
                int kr = kq * 16 + (lane & 15);
                int nc = ncb + nj * 2 + (lane >> 4);
                uint32_t bd = (uint32_t)(kr * 256 + ((nc ^ (kr & 7)) << 4));
                LDSM4T(bh[nj][0], bh[nj][1], bh[nj][2], bh[nj][3], sbh + bd);
                LDSM4T(bl[nj][0], bl[nj][1], bl[nj][2], bl[nj][3], sbl + bd);
            }
#pragma unroll
            for (int mi = 0; mi < 4; mi++)
#pragma unroll
                for (int nt = 0; nt < 8; nt++) {
                    int nj = nt >> 1, pq = (nt & 1) * 2;
                    MMA_F16(acc[mi][nt], ar[mi], bh[nj][pq], bh[nj][pq + 1]);
                    MMA_F16(acc[mi][nt], ar[mi], bl[nj][pq], bl[nj][pq + 1]);
                }
        }
    };

    load_chunk(0, 0);
    for (int ch = 0; ch < 8; ch++) {
        if (ch < 7) { load_chunk(ch + 1, (ch + 1) & 1); CP_WAIT(1); }
        else        { CP_WAIT(0); }
        __syncthreads();
        compute(sb + (ch & 1) * MSTAGE);
        __syncthreads();
    }

    // ---- epilogue: write g_ha, LN partials via shuffle reduce ----
    float s = 0.f, ss = 0.f;
    int rbase = T * 128 + wm + (lane >> 2);
    int cbase = nh * 128 + wn + (lane & 3) * 2;
#pragma unroll
    for (int mi = 0; mi < 4; mi++) {
        int r0 = rbase + mi * 16;
        int r1 = r0 + 8;
        bool v0 = r0 < nvalid, v1 = r1 < nvalid;
#pragma unroll
        for (int nt = 0; nt < 8; nt++) {
            int col = cbase + nt * 8;
            if (v0) {
                float2 p = make_float2(acc[mi][nt][0], acc[mi][nt][1]);
                *(float2*)&g_ha[(size_t)r0 * DH + col] = p;
                s += p.x + p.y; ss += p.x * p.x + p.y * p.y;
            }
            if (v1) {
                float2 p = make_float2(acc[mi][nt][2], acc[mi][nt][3]);
                *(float2*)&g_ha[(size_t)r1 * DH + col] = p;
                s += p.x + p.y; ss += p.x * p.x + p.y * p.y;
            }
        }
    }
#pragma unroll
    for (int o = 16; o > 0; o >>= 1) {
        s += __shfl_xor_sync(0xffffffffu, s, o);
        ss += __shfl_xor_sync(0xffffffffu, ss, o);
    }
    __syncthreads();
    float* red = (float*)smem;
    if (lane == 0) { red[wid] = s; red[4 + wid] = ss; }
    __syncthreads();
    if (tid == 0) {
        float a = 0.f, b = 0.f;
#pragma unroll
        for (int i = 0; i < 4; i++) { a += red[i]; b += red[4 + i]; }
        int slot = nh * mtG + T;
        g_part[slot] = a; g_part2[slot] = b;
    }
}

// ---------------- lin1: fp16 2-pass, 128m x 256n, K=128 (2x64) ----------------
#define STAGE 81920u
#define SMTOT 163840
__global__ __launch_bounds__(256, 1) void k_lin1(const float* __restrict__ bias, int nvalid) {
    extern __shared__ char smem[];
    uint32_t sb = s2u(smem);
    const int tid = threadIdx.x, lane = tid & 31, wid = tid >> 5;
    const int T = blockIdx.x;

    auto load_chunk = [&](int c, int st) {
        uint32_t s0 = sb + st * STAGE;
#pragma unroll
        for (int i = 0; i < 4; i++) {
            int e = tid + i * 256;
            int m = e >> 3, kc = e & 7;
            uint32_t da = (uint32_t)(m * 128 + ((kc ^ (m & 7)) << 4));
            cp16(s0 + da, g_x16 + (size_t)(T * 128 + m) * 128 + c * 64 + kc * 8);
        }
#pragma unroll
        for (int i = 0; i < 8; i++) {
            int e = tid + i * 256;
            int k = e >> 5, ncol = e & 31;
            int nhalf = ncol >> 4, nc = ncol & 15;
            uint32_t db = (uint32_t)(nhalf * 16384 + k * 256 + ((nc ^ (k & 7)) << 4));
            size_t src = (size_t)(c * 64 + k) * 256 + nhalf * 128 + nc * 8;
            cp16(s0 + 16384 + db, g_w1h + src);
            cp16(s0 + 49152 + db, g_w1l + src);
        }
        CP_COMMIT();
    };

    float acc[4][8][4];
#pragma unroll
    for (int i = 0; i < 4; i++)
#pragma unroll
        for (int j = 0; j < 8; j++)
#pragma unroll
            for (int q = 0; q < 4; q++) acc[i][j][q] = 0.f;

    const int wm = (wid & 1) * 64;
    const int wng = (wid >> 1) * 64;
    const uint32_t nhb = (uint32_t)((wng >> 7) * 16384);
    const int ncb = (wng & 127) >> 3;

    auto compute = [&](uint32_t s0) {
        uint32_t sa = s0, sbh = s0 + 16384, sbl = s0 + 49152;
#pragma unroll
        for (int kq = 0; kq < 4; kq++) {
            uint32_t ar[4][4], bh[4][4], bl[4][4];
#pragma unroll
            for (int mi = 0; mi < 4; mi++) {
                int m = wm + mi * 16 + (lane & 15);
                int kcc = kq * 2 + (lane >> 4);
                uint32_t ad = (uint32_t)(m * 128 + ((kcc ^ (m & 7)) << 4));
                LDSM4(ar[mi][0], ar[mi][1], ar[mi][2], ar[mi][3], sa + ad);
            }
#pragma unroll
            for (int nj = 0; nj < 4; nj++) {
                int kr = kq * 16 + (lane & 15);
                int nc = ncb + nj * 2 + (lane >> 4);
                uint32_t bd = nhb + (uint32_t)(kr * 256 + ((nc ^ (kr & 7)) << 4));
                LDSM4T(bh[nj][0], bh[nj][1], bh[nj][2], bh[nj][3], sbh + bd);
                LDSM4T(bl[nj][0], bl[nj][1], bl[nj][2], bl[nj][3], sbl + bd);
            }
#pragma unroll
            for (int mi = 0; mi < 4; mi++)
#pragma unroll
                for (int nt = 0; nt < 8; nt++) {
                    int nj = nt >> 1, pq = (nt & 1) * 2;
                    MMA_F16(acc[mi][nt], ar[mi], bh[nj][pq], bh[nj][pq + 1]);
                    MMA_F16(acc[mi][nt], ar[mi], bl[nj][pq], bl[nj][pq + 1]);
                }
        }
    };

    load_chunk(0, 0);
    load_chunk(1, 1);
    CP_WAIT(1);
    __syncthreads();
    compute(sb);
    __syncthreads();
    CP_WAIT(0);
    __syncthreads();
    compute(sb + STAGE);

    int rbase = T * 128 + wm + (lane >> 2);
    int cbase = wng + (lane & 3) * 2;
#pragma unroll
    for (int mi = 0; mi < 4; mi++) {
        int r0 = rbase + mi * 16;
        int r1 = r0 + 8;
        float d0 = (r0 < nvalid) ? g_dis[r0] : 0.f;
        float d1 = (r1 < nvalid) ? g_dis[r1] : 0.f;
#pragma unroll
        for (int nt = 0; nt < 8; nt++) {
            int col = cbase + nt * 8;
            float2 bb = *(const float2*)&bias[col];
            float v0 = fmaxf(acc[mi][nt][0] + bb.x, 0.f);
            float v1 = fmaxf(acc[mi][nt][1] + bb.y, 0.f);
            *(__half2*)&g_a[(size_t)r0 * 512 + 256 + col] = __floats2half2_rn(v0, v1);
            if (r0 < nvalid)
                *(__half2*)&g_hn[(size_t)r0 * DH + col] = __floats2half2_rn(v0 * d0, v1 * d0);
            float v2 = fmaxf(acc[mi][nt][2] + bb.x, 0.f);
            float v3 = fmaxf(acc[mi][nt][3] + bb.y, 0.f);
            *(__half2*)&g_a[(size_t)r1 * 512 + 256 + col] = __floats2half2_rn(v2, v3);
            if (r1 < nvalid)
                *(__half2*)&g_hn[(size_t)r1 * DH + col] = __floats2half2_rn(v2 * d1, v3 * d1);
        }
    }
}

// ---------------- lin2: fp16 2-pass, 256m x 128n, K=256 (4x64) ----------------
#define L2STAGE 65536u
#define L2SMTOT 131072
__global__ __launch_bounds__(256, 1) void k_lin2(const float* __restrict__ bias,
                                                 float* __restrict__ out, int nvalid) {
    extern __shared__ char smem[];
    uint32_t sb = s2u(smem);
    const int tid = threadIdx.x, lane = tid & 31, wid = tid >> 5;
    const int T = blockIdx.x;

    auto load_chunk = [&](int c, int st) {
        uint32_t s0 = sb + st * L2STAGE;
#pragma unroll
        for (int i = 0; i < 8; i++) {
            int e = tid + i * 256;
            int m = e >> 3, kc = e & 7;
            uint32_t da = (uint32_t)(m * 128 + ((kc ^ (m & 7)) << 4));
            cp16(s0 + da, g_hn + (size_t)(T * 256 + m) * DH + c * 64 + kc * 8);
        }
#pragma unroll
        for (int i = 0; i < 4; i++) {
            int e = tid + i * 256;
            int k = e >> 4, nc = e & 15;
            uint32_t db = (uint32_t)(k * 256 + ((nc ^ (k & 7)) << 4));
            size_t src = (size_t)(c * 64 + k) * 128 + nc * 8;
            cp16(s0 + 32768 + db, g_w2h + src);
            cp16(s0 + 49152 + db, g_w2l + src);
        }
        CP_COMMIT();
    };

    float acc[4][8][4];
#pragma unroll
    for (int i = 0; i < 4; i++)
#pragma unroll
        for (int j = 0; j < 8; j++)
#pragma unroll
            for (int q = 0; q < 4; q++) acc[i][j][q] = 0.f;

    const int wm = (wid & 3) * 64;
    const int wn = (wid >> 2) * 64;
    const int ncb = wn >> 3;

    auto compute = [&](uint32_t s0) {
        uint32_t sa = s0, sbh = s0 + 32768, sbl = s0 + 49152;
#pragma unroll
        for (int kq = 0; kq < 4; kq++) {
            uint32_t ar[4][4], bh[4][4], bl[4][4];
#pragma unroll
            for (int mi = 0; mi < 4; mi++) {
                int m = wm + mi * 16 + (lane & 15);
                int kcc = kq * 2 + (lane >> 4);
                uint32_t ad = (uint32_t)(m * 128 + ((kcc ^ (m & 7)) << 4));
                LDSM4(ar[mi][0], ar[mi][1], ar[mi][2], ar[mi][3], sa + ad);
            }
#pragma unroll
            for (int nj = 0; nj < 4; nj++) {
                int kr = kq * 16 + (lane & 15);
                int nc = ncb + nj * 2 + (lane >> 4);
                uint32_t bd = (uint32_t)(kr * 256 + ((nc ^ (kr & 7)) << 4));
                LDSM4T(bh[nj][0], bh[nj][1], bh[nj][2], bh[nj][3], sbh + bd);
                LDSM4T(bl[nj][0], bl[nj][1], bl[nj][2], bl[nj][3], sbl + bd);
            }
#pragma unroll
            for (int mi = 0; mi < 4; mi++)
#pragma unroll
                for (int nt = 0; nt < 8; nt++) {
                    int nj = nt >> 1, pq = (nt & 1) * 2;
                    MMA_F16(acc[mi][nt], ar[mi], bh[nj][pq], bh[nj][pq + 1]);
                    MMA_F16(acc[mi][nt], ar[mi], bl[nj][pq], bl[nj][pq + 1]);
                }
        }
    };

    load_chunk(0, 0);
    for (int ch = 0; ch < 4; ch++) {
        if (ch < 3) { load_chunk(ch + 1, (ch + 1) & 1); CP_WAIT(1); }
        else        { CP_WAIT(0); }
        __syncthreads();
        compute(sb + (ch & 1) * L2STAGE);
        __syncthreads();
    }

    int rbase = T * 256 + wm + (lane >> 2);
    int cbase = wn + (lane & 3) * 2;
#pragma unroll
    for (int mi = 0; mi < 4; mi++) {
        int r0 = rbase + mi * 16;
        int r1 = r0 + 8;
        bool v0 = r0 < nvalid, v1 = r1 < nvalid;
#pragma unroll
        for (int nt = 0; nt < 8; nt++) {
            int col = cbase + nt * 8;
            float2 bb = *(const float2*)&bias[col];
            if (v0) {
                float2 p = make_float2(fmaxf(acc[mi][nt][0] + bb.x, 0.f),
                                       fmaxf(acc[mi][nt][1] + bb.y, 0.f));
                *(float2*)&out[(size_t)r0 * 128 + col] = p;
            }
            if (v1) {
                float2 p = make_float2(fmaxf(acc[mi][nt][2] + bb.x, 0.f),
                                       fmaxf(acc[mi][nt][3] + bb.y, 0.f));
                *(float2*)&out[(size_t)r1 * 128 + col] = p;
            }
        }
    }
}

// ---------------- layernorm: finalize + normalize+relu (+dis prescale) ----------------
__global__ __launch_bounds__(256) void k_norm(const float* __restrict__ gamma,
                                              const float* __restrict__ beta,
                                              int total4, int nparts, float invcnt, int scale_dis) {
    __shared__ float sred[512];
    __shared__ float s_scale[256], s_shift[256];
    const int tid = threadIdx.x;

    float s = 0.f, ss = 0.f;
    for (int i = tid; i < nparts; i += 256) { s += g_part[i]; ss += g_part2[i]; }
    sred[tid] = s; sred[256 + tid] = ss;
    __syncthreads();
    for (int o = 128; o > 0; o >>= 1) {
        if (tid < o) { sred[tid] += sred[tid + o]; sred[256 + tid] += sred[256 + tid + o]; }
        __syncthreads();
    }
    float mu = sred[0] * invcnt;
    float var = fmaxf(sred[256] * invcnt - mu * mu, 0.f);
    float inv = 1.0f / (sqrtf(var) + 1e-5f);
    float gch = gamma[tid] * inv;
    s_scale[tid] = gch;
    s_shift[tid] = beta[tid] - mu * gch;
    __syncthreads();

    int stride = gridDim.x * 256;
    for (int i = blockIdx.x * 256 + tid; i < total4; i += stride) {
        float4 v = ((const float4*)g_ha)[i];
        int f = (i * 4) & 255;
        int node = i >> 6;
        float d = scale_dis ? g_dis[node] : 1.0f;
        float4 g = *(float4*)&s_scale[f];
        float4 b = *(float4*)&s_shift[f];
        v.x = fmaxf(fmaf(v.x, g.x, b.x), 0.f) * d;
        v.y = fmaxf(fmaf(v.y, g.y, b.y), 0.f) * d;
        v.z = fmaxf(fmaf(v.z, g.z, b.z), 0.f) * d;
        v.w = fmaxf(fmaf(v.w, g.w, b.w), 0.f) * d;
        __half2* dst = (__half2*)&g_hn[(size_t)i * 4];
        dst[0] = __floats2half2_rn(v.x, v.y);
        dst[1] = __floats2half2_rn(v.z, v.w);
    }
}

// ---------------- launch ----------------
extern "C" void kernel_launch(void* const* d_in, const int* in_sizes, int n_in,
                              void* d_out, int out_size) {
    const float* x      = (const float*)d_in[0];
    const int*   ei     = (const int*)d_in[1];
    const float* lin1_w = (const float*)d_in[2];
    const float* lin1_b = (const float*)d_in[3];
    const float* w1     = (const float*)d_in[4];
    const float* w2     = (const float*)d_in[5];
    const float* gamma  = (const float*)d_in[6];
    const float* betab  = (const float*)d_in[7];
    const float* lin2_w = (const float*)d_in[8];
    const float* lin2_b = (const float*)d_in[9];
    float* out = (float*)d_out;

    int N = in_sizes[0] / 128;
    int E = in_sizes[1] / 2;
    const int* row = ei;
    const int* col = ei + E;

    int Mt = (N + 127) / 128;
    int Mt2 = (N + 255) / 256;
    int total4 = N * (DH / 4);
    float invcnt = 1.0f / ((float)N * (float)DH);
    int xtotal = N * 128;
    int prep_total = PB_ELEMS + xtotal + 128 * 256 + 256 * 128 + N;
    int npairs = (N + 1) / 2;

    static int smem_set = 0;
    if (!smem_set) {
        cudaFuncSetAttribute(k_mma, cudaFuncAttributeMaxDynamicSharedMemorySize, MSMTOT);
        cudaFuncSetAttribute(k_lin1, cudaFuncAttributeMaxDynamicSharedMemorySize, SMTOT);
        cudaFuncSetAttribute(k_lin2, cudaFuncAttributeMaxDynamicSharedMemorySize, L2SMTOT);
        smem_set = 1;
    }

    k_prep_all<<<(prep_total + 255) / 256, 256>>>(w1, w2, x, xtotal, lin1_w, lin2_w, N);
    k_count<<<(E + 255) / 256, 256>>>(col, E);
    k_scan<<<1, 1024>>>(N, E);
    k_scatter<<<(E + 255) / 256, 256>>>(row, col, E);

    k_lin1<<<Mt, 256, SMTOT>>>(lin1_b, N);

    for (int l = 0; l < NL; l++) {
        k_gather<<<(npairs * 32 + 255) / 256, 256>>>(N);
        k_mma<<<dim3(Mt, 2), 128, MSMTOT>>>(l, N, Mt);
        k_norm<<<1184, 256>>>(gamma + l * DH, betab + l * DH, total4, Mt * 2, invcnt,
                              (l < NL - 1) ? 1 : 0);
    }

    k_lin2<<<Mt2, 256, L2SMTOT>>>(lin2_b, out, N);
}